// round 3
// baseline (speedup 1.0000x reference)
#include <cuda_runtime.h>

// ---------------- problem constants ----------------
#define NB   256      // batch
#define TQ   64       // quantized time
#define HD   256      // hidden dim
#define KC   8192     // n_embeddings

// output packing: (out, codebook_loss, commitment_loss, indices)
#define OUT_ELEMS   (256*1024*32)      // 8388608
#define LOSS_OFF    OUT_ELEMS
#define IDX_OFF     (OUT_ELEMS + 2)

// transposed-weight offsets
#define WT0  0          // enc0 32*3*64   = 6144
#define WT1  6144       // enc1 64*3*128  = 24576
#define WT2  30720      // enc2 128*3*256 = 98304
#define WTP  129024     // proj 256*1*256 = 65536
#define WTD0 194560     // dec0 256*3*256 = 196608
#define WTD1 391168     // dec1 256*3*128 = 98304
#define WTD2 489472     // dec2 128*3*64  = 24576
#define WTD3 514048     // dec3 64*3*32   = 6144
#define WTTOT 520192

typedef unsigned long long u64;

// ---------------- f32x2 helpers (sm_103a packed fp32, bit-identical to 2x scalar) ----
__device__ __forceinline__ u64 ffma2(u64 a, u64 b, u64 c) {
    u64 d;
    asm("fma.rn.f32x2 %0, %1, %2, %3;" : "=l"(d) : "l"(a), "l"(b), "l"(c));
    return d;
}
__device__ __forceinline__ u64 pack2(float lo, float hi) {
    u64 d;
    asm("mov.b64 %0, {%1, %2};" : "=l"(d) : "f"(lo), "f"(hi));
    return d;
}
__device__ __forceinline__ float f2lo(u64 v) {
    float lo, hi;
    asm("mov.b64 {%0, %1}, %2;" : "=f"(lo), "=f"(hi) : "l"(v));
    return lo;
}
__device__ __forceinline__ float f2hi(u64 v) {
    float lo, hi;
    asm("mov.b64 {%0, %1}, %2;" : "=f"(lo), "=f"(hi) : "l"(v));
    return hi;
}

// ---------------- device scratch ----------------
__device__ float g_h0[256*64*256];
__device__ float g_h1[256*128*128];
__device__ float g_h2[256*256*64];
__device__ float g_ze[256*256*64];
__device__ float g_zq[256*256*64];
__device__ float g_d0[256*256*128];
__device__ float g_d1[256*128*256];
__device__ float g_d2[256*64*512];
__device__ float g_wt[WTTOT];
__device__ float g_hn[KC];
__device__ int   g_idx[NB*TQ];
__device__ float g_loss[1];

// ---------------- combined weight transpose: w[co][ci][k] -> wt[(ci*K+k)][co] -----
struct WtArgs {
    const float* src[8];
    int dst_off[8];
    int cout[8];
    int cink[8];
    int start[8];   // cumulative element start (start[0]=0)
    int total;
};
__global__ void wtrans_all_kernel(WtArgs a, float* __restrict__ wt) {
    int i = blockIdx.x * 256 + threadIdx.x;
    if (i >= a.total) return;
    int s = 0;
    #pragma unroll
    for (int q = 1; q < 8; q++) if (i >= a.start[q]) s = q;
    int e  = i - a.start[s];
    int co = e / a.cink[s];
    int r  = e - co * a.cink[s];
    wt[a.dst_off[s] + r * a.cout[s] + co] = a.src[s][e];
}

// ---------------- 0.5*||e||^2 (+ zero loss accumulator) ----------------
__global__ void enorm_kernel(const float* __restrict__ emb) {
    if (blockIdx.x == 0 && threadIdx.x == 0) g_loss[0] = 0.f;
    int n = blockIdx.x * 8 + (threadIdx.x >> 5);
    int lane = threadIdx.x & 31;
    const float* e = emb + (long)n * HD;
    float s = 0.f;
    #pragma unroll
    for (int c = lane; c < HD; c += 32) { float v = e[c]; s += v * v; }
    #pragma unroll
    for (int o = 16; o; o >>= 1) s += __shfl_xor_sync(0xffffffffu, s, o);
    if (lane == 0) g_hn[n] = 0.5f * s;
}

// ---------------- generic direct conv1d (k=3, strided; encoder) ----------------
template<int CIN, int COUT, int TT, int STRIDE, int PAD, bool RELU>
__global__ void conv1d_kernel(const float* __restrict__ in, const float* __restrict__ wt,
                              const float* __restrict__ bias, float* __restrict__ out,
                              int Tin, int Tout, int inB, int inC, int inT) {
    const int SW = STRIDE * (TT - 1) + 3;
    __shared__ float s_in[CIN][SW];
    int b   = blockIdx.x;
    int to0 = blockIdx.y * TT;
    int ti0 = STRIDE * to0 - PAD;

    for (int idx = threadIdx.x; idx < CIN * SW; idx += blockDim.x) {
        int ci = idx / SW, j = idx - ci * SW;
        int tg = ti0 + j;
        s_in[ci][j] = (tg >= 0 && tg < Tin)
            ? in[(long)b * inB + (long)ci * inC + (long)tg * inT] : 0.f;
    }
    __syncthreads();

    int co = threadIdx.x;
    float acc[TT];
    float bv = bias[co];
    #pragma unroll
    for (int t = 0; t < TT; t++) acc[t] = bv;

    for (int ci = 0; ci < CIN; ci++) {
        const float* sr = s_in[ci];
        float w0 = wt[(ci * 3 + 0) * COUT + co];
        float w1 = wt[(ci * 3 + 1) * COUT + co];
        float w2 = wt[(ci * 3 + 2) * COUT + co];
        #pragma unroll
        for (int t = 0; t < TT; t++) {
            acc[t] = fmaf(w0, sr[STRIDE * t + 0], acc[t]);
            acc[t] = fmaf(w1, sr[STRIDE * t + 1], acc[t]);
            acc[t] = fmaf(w2, sr[STRIDE * t + 2], acc[t]);
        }
    }
    long ob = (long)b * COUT * Tout + (long)co * Tout + to0;
    #pragma unroll
    for (int t = 0; t < TT; t++) {
        float v = acc[t];
        if (RELU) v = fmaxf(v, 0.f);
        out[ob + t] = v;
    }
}

// ---------------- 1x1 projection conv, f32x2 ----------------
__global__ void proj_kernel(const float* __restrict__ in, const float* __restrict__ wt,
                            const float* __restrict__ bias, float* __restrict__ out) {
    __shared__ float s_in[256][16];
    int b   = blockIdx.x;
    int to0 = blockIdx.y * 16;
    for (int idx = threadIdx.x; idx < 256 * 16; idx += 256) {
        int ci = idx >> 4, j = idx & 15;
        s_in[ci][j] = in[(long)b * (256 * 64) + ci * 64 + to0 + j];
    }
    __syncthreads();

    int co = threadIdx.x;
    float bv = bias[co];
    u64 acc[8];
    #pragma unroll
    for (int p = 0; p < 8; p++) acc[p] = pack2(bv, bv);

    for (int ci = 0; ci < 256; ci++) {
        float w = wt[ci * 256 + co];
        u64 ws = pack2(w, w);
        const u64* xr = (const u64*)&s_in[ci][0];
        #pragma unroll
        for (int p = 0; p < 8; p++) acc[p] = ffma2(ws, xr[p], acc[p]);
    }
    long ob = (long)b * (256 * 64) + (long)co * 64 + to0;
    #pragma unroll
    for (int p = 0; p < 8; p++) {
        out[ob + 2 * p + 0] = f2lo(acc[p]);
        out[ob + 2 * p + 1] = f2hi(acc[p]);
    }
}

// ---------------- deconv (ConvTranspose1d k=3 s=2 p=1 op=1), f32x2 ----------------
template<int CIN, int COUT, int TT, int G, bool RELU>
__global__ void deconv1d_kernel(const float* __restrict__ in, const float* __restrict__ wt,
                                const float* __restrict__ bias, float* __restrict__ out,
                                int Tin, long oB, long oCs, long oTs) {
    const int IW  = G * TT / 2 + 1;
    const int IWP = (IW | 1) + 1;
    __shared__ float s_in[CIN][IWP];
    int b   = blockIdx.x;
    int to0 = blockIdx.y * (G * TT);
    int t0h = to0 >> 1;
    int nt  = blockDim.x * blockDim.y;
    int tid = threadIdx.y * blockDim.x + threadIdx.x;

    for (int idx = tid; idx < CIN * IW; idx += nt) {
        int ci = idx / IW, j = idx - ci * IW;
        int tg = t0h + j;
        s_in[ci][j] = (tg < Tin) ? in[(long)b * CIN * Tin + (long)ci * Tin + tg] : 0.f;
    }
    __syncthreads();

    int co   = threadIdx.x;
    int base = threadIdx.y * TT;
    int H0   = base >> 1;
    float bv = bias[co];
    u64 aE[TT / 4], aO[TT / 4];
    #pragma unroll
    for (int p = 0; p < TT / 4; p++) { aE[p] = pack2(bv, bv); aO[p] = pack2(bv, bv); }

    for (int ci = 0; ci < CIN; ci++) {
        float w0 = wt[(ci * 3 + 0) * COUT + co];
        float w1 = wt[(ci * 3 + 1) * COUT + co];
        float w2 = wt[(ci * 3 + 2) * COUT + co];
        u64 w00 = pack2(w0, w0), w11 = pack2(w1, w1), w22 = pack2(w2, w2);
        const float2* xr = (const float2*)(&s_in[ci][H0]);
        float2 xp[4];
        #pragma unroll
        for (int p = 0; p < 4; p++) xp[p] = xr[p];
        float x8 = s_in[ci][H0 + 8];
        #pragma unroll
        for (int p = 0; p < 4; p++) {
            u64 X = pack2(xp[p].x, xp[p].y);
            u64 Z = pack2(xp[p].y, (p < 3) ? xp[p + 1].x : x8);
            aE[p] = ffma2(w11, X, aE[p]);
            aO[p] = ffma2(w00, X, aO[p]);
            aO[p] = ffma2(w22, Z, aO[p]);
        }
    }
    long ob = (long)b * oB + (long)co * oCs;
    #pragma unroll
    for (int p = 0; p < 4; p++) {
        float v0 = f2lo(aE[p]), v1 = f2lo(aO[p]), v2 = f2hi(aE[p]), v3 = f2hi(aO[p]);
        if (RELU) { v0 = fmaxf(v0, 0.f); v1 = fmaxf(v1, 0.f); v2 = fmaxf(v2, 0.f); v3 = fmaxf(v3, 0.f); }
        long t = to0 + base + 4 * p;
        out[ob + (t + 0) * oTs] = v0;
        out[ob + (t + 1) * oTs] = v1;
        out[ob + (t + 2) * oTs] = v2;
        out[ob + (t + 3) * oTs] = v3;
    }
}

// ---------------- VQ: fused GEMM (Z @ E^T) + argmax(score - 0.5||e||^2) --------------
// One CTA per batch (64 rows). A stored DUPLICATED in smem (zero-pack FFMA2 operand);
// B undup k-major, 32-wide n tiles, double-buffered via reg-staged coalesced LDG.
// Per k per thread: 4 FFMA2 + 2 LDS.128 = 6 issues, FMA-pipe-bound.
#define BROW 36                                   // B row stride (floats), 16B multiple
#define VQ_SMEM (256*128*4 + 2*256*BROW*4)        // 131072 + 73728 = 204800
__global__ void vq_kernel(const float* __restrict__ ze, const float* __restrict__ emb,
                          const float* __restrict__ hn, int* __restrict__ out_idx) {
    extern __shared__ float sm[];
    float* Asd = sm;                       // [256][128]  Asd[k][2m]=Asd[k][2m+1]=a
    float* Bs0 = sm + 256 * 128;           // [256][BROW] k-major
    float* Bs1 = Bs0 + 256 * BROW;
    int b   = blockIdx.x;
    int tid = threadIdx.x;                 // 256
    int tx  = tid & 7;                     // n quad: n_local = 4*tx
    int ty  = tid >> 3;                    // m pair: m0 = 2*ty
    int n_l = tid >> 3;                    // fill: n row 0..31
    int kq  = tid & 7;                     // fill: k quad

    // ---- fill Asd (duplicated z tile), coalesced reads ----
    const float* zb = ze + (long)b * (HD * TQ);
    #pragma unroll 4
    for (int i = 0; i < 64; i++) {
        int el = i * 256 + tid;            // el = k*64 + t
        float v = zb[el];
        int k = el >> 6, t = el & 63;
        Asd[k * 128 + 2 * t]     = v;
        Asd[k * 128 + 2 * t + 1] = v;
    }

    // ---- fill tile 0 (coalesced row-major LDG -> transposed STS) ----
    {
        const float* eb = emb + (long)n_l * HD + kq * 4;
        #pragma unroll
        for (int c = 0; c < 8; c++) {
            float4 v = *(const float4*)(eb + 32 * c);
            int k = kq * 4 + 32 * c;
            Bs0[(k + 0) * BROW + n_l] = v.x;
            Bs0[(k + 1) * BROW + n_l] = v.y;
            Bs0[(k + 2) * BROW + n_l] = v.z;
            Bs0[(k + 3) * BROW + n_l] = v.w;
        }
    }
    __syncthreads();

    float bval0 = -3.4e38f, bval1 = -3.4e38f;
    int   bidx0 = 0,        bidx1 = 0;
    const float* ab = Asd + 4 * ty;

    for (int tile = 0; tile < KC / 32; tile++) {
        const float* cur = (tile & 1) ? Bs1 : Bs0;
        float*       nxt = (tile & 1) ? Bs0 : Bs1;

        // prefetch next tile into registers (latency hidden by mainloop)
        float4 pf[8];
        bool more = (tile + 1) < KC / 32;
        if (more) {
            const float* eb = emb + (long)((tile + 1) * 32 + n_l) * HD + kq * 4;
            #pragma unroll
            for (int c = 0; c < 8; c++) pf[c] = *(const float4*)(eb + 32 * c);
        }

        u64 acc0 = 0ull, acc1 = 0ull, acc2 = 0ull, acc3 = 0ull;
        const float* bb = cur + 4 * tx;
        #pragma unroll 8
        for (int k = 0; k < HD; k++) {
            ulonglong2 av = *(const ulonglong2*)(ab + 128 * k);   // (a_m0,a_m0),(a_m1,a_m1)
            ulonglong2 bv = *(const ulonglong2*)(bb + BROW * k);  // (b_n0,b_n1),(b_n2,b_n3)
            acc0 = ffma2(av.x, bv.x, acc0);
            acc1 = ffma2(av.x, bv.y, acc1);
            acc2 = ffma2(av.y, bv.x, acc2);
            acc3 = ffma2(av.y, bv.y, acc3);
        }

        // epilogue: scores & argmax update (ascending n, strict >)
        int n0 = tile * 32 + 4 * tx;
        float4 h = *(const float4*)&hn[n0];
        {
            float s0 = f2lo(acc0) - h.x, s1 = f2hi(acc0) - h.y;
            float s2 = f2lo(acc1) - h.z, s3 = f2hi(acc1) - h.w;
            if (s0 > bval0) { bval0 = s0; bidx0 = n0 + 0; }
            if (s1 > bval0) { bval0 = s1; bidx0 = n0 + 1; }
            if (s2 > bval0) { bval0 = s2; bidx0 = n0 + 2; }
            if (s3 > bval0) { bval0 = s3; bidx0 = n0 + 3; }
        }
        {
            float s0 = f2lo(acc2) - h.x, s1 = f2hi(acc2) - h.y;
            float s2 = f2lo(acc3) - h.z, s3 = f2hi(acc3) - h.w;
            if (s0 > bval1) { bval1 = s0; bidx1 = n0 + 0; }
            if (s1 > bval1) { bval1 = s1; bidx1 = n0 + 1; }
            if (s2 > bval1) { bval1 = s2; bidx1 = n0 + 2; }
            if (s3 > bval1) { bval1 = s3; bidx1 = n0 + 3; }
        }

        // store prefetched tile, then barrier before it is consumed
        if (more) {
            #pragma unroll
            for (int c = 0; c < 8; c++) {
                int k = kq * 4 + 32 * c;
                nxt[(k + 0) * BROW + n_l] = pf[c].x;
                nxt[(k + 1) * BROW + n_l] = pf[c].y;
                nxt[(k + 2) * BROW + n_l] = pf[c].z;
                nxt[(k + 3) * BROW + n_l] = pf[c].w;
            }
        }
        __syncthreads();
    }

    // ---- reduce over the 8 tx lanes sharing each m (tie-break: lower index) ----
    #pragma unroll
    for (int s = 1; s < 8; s <<= 1) {
        float ov0 = __shfl_xor_sync(0xffffffffu, bval0, s);
        int   oi0 = __shfl_xor_sync(0xffffffffu, bidx0, s);
        float ov1 = __shfl_xor_sync(0xffffffffu, bval1, s);
        int   oi1 = __shfl_xor_sync(0xffffffffu, bidx1, s);
        if (ov0 > bval0 || (ov0 == bval0 && oi0 < bidx0)) { bval0 = ov0; bidx0 = oi0; }
        if (ov1 > bval1 || (ov1 == bval1 && oi1 < bidx1)) { bval1 = ov1; bidx1 = oi1; }
    }
    if (tx == 0) {
        out_idx[b * 64 + 2 * ty]     = bidx0;
        out_idx[b * 64 + 2 * ty + 1] = bidx1;
    }
}

// ---------------- gather z_q + loss sum ----------------
__global__ void loss_gather_kernel(const float* __restrict__ ze, const float* __restrict__ emb) {
    int m = blockIdx.x;
    int b = m >> 6, t = m & 63;
    int c = threadIdx.x;                      // 256
    int e = g_idx[m];
    float q = emb[(long)e * HD + c];
    long zoff = (long)b * (HD * TQ) + (long)c * TQ + t;
    float z = ze[zoff];
    g_zq[zoff] = q;
    float d = z - q;
    float s = d * d;
    #pragma unroll
    for (int o = 16; o; o >>= 1) s += __shfl_down_sync(0xffffffffu, s, o);
    __shared__ float ws[8];
    if ((c & 31) == 0) ws[c >> 5] = s;
    __syncthreads();
    if (c == 0) {
        float tot = 0.f;
        #pragma unroll
        for (int i = 0; i < 8; i++) tot += ws[i];
        atomicAdd(g_loss, tot);
    }
}

// ---------------- indices + losses to output ----------------
__global__ void idxout_kernel(float* out) {
    int m = blockIdx.x * 256 + threadIdx.x;
    out[IDX_OFF + m] = (float)g_idx[m];
    if (m == 0) {
        float l = g_loss[0] * (1.f / 4194304.f);   // mean over B*H*TQ
        out[LOSS_OFF + 0] = l;
        out[LOSS_OFF + 1] = l;
    }
}

// ---------------- launch ----------------
extern "C" void kernel_launch(void* const* d_in, const int* in_sizes, int n_in,
                              void* d_out, int out_size) {
    const float* x   = (const float*)d_in[0];
    const float* ew0 = (const float*)d_in[1];  const float* eb0 = (const float*)d_in[2];
    const float* ew1 = (const float*)d_in[3];  const float* eb1 = (const float*)d_in[4];
    const float* ew2 = (const float*)d_in[5];  const float* eb2 = (const float*)d_in[6];
    const float* pw  = (const float*)d_in[7];  const float* pb  = (const float*)d_in[8];
    const float* emb = (const float*)d_in[9];
    const float* dw0 = (const float*)d_in[10]; const float* db0 = (const float*)d_in[11];
    const float* dw1 = (const float*)d_in[12]; const float* db1 = (const float*)d_in[13];
    const float* dw2 = (const float*)d_in[14]; const float* db2 = (const float*)d_in[15];
    const float* dw3 = (const float*)d_in[16]; const float* db3 = (const float*)d_in[17];
    float* out = (float*)d_out;

    void* p;
    cudaGetSymbolAddress(&p, g_wt);  float* wt = (float*)p;
    cudaGetSymbolAddress(&p, g_h0);  float* h0 = (float*)p;
    cudaGetSymbolAddress(&p, g_h1);  float* h1 = (float*)p;
    cudaGetSymbolAddress(&p, g_h2);  float* h2 = (float*)p;
    cudaGetSymbolAddress(&p, g_ze);  float* ze = (float*)p;
    cudaGetSymbolAddress(&p, g_zq);  float* zq = (float*)p;
    cudaGetSymbolAddress(&p, g_d0);  float* d0 = (float*)p;
    cudaGetSymbolAddress(&p, g_d1);  float* d1 = (float*)p;
    cudaGetSymbolAddress(&p, g_d2);  float* d2 = (float*)p;
    cudaGetSymbolAddress(&p, g_hn);  float* hn = (float*)p;
    cudaGetSymbolAddress(&p, g_idx); int*   ix = (int*)p;

    cudaFuncSetAttribute(vq_kernel, cudaFuncAttributeMaxDynamicSharedMemorySize, VQ_SMEM);

    // prep: combined weight transpose, code norms (+loss zero)
    WtArgs wa;
    const float* srcs[8] = {ew0, ew1, ew2, pw, dw0, dw1, dw2, dw3};
    int offs[8]  = {WT0, WT1, WT2, WTP, WTD0, WTD1, WTD2, WTD3};
    int couts[8] = {64, 128, 256, 256, 256, 128, 64, 32};
    int cinks[8] = {32*3, 64*3, 128*3, 256, 256*3, 256*3, 128*3, 64*3};
    int acc = 0;
    for (int q = 0; q < 8; q++) {
        wa.src[q] = srcs[q]; wa.dst_off[q] = offs[q];
        wa.cout[q] = couts[q]; wa.cink[q] = cinks[q];
        wa.start[q] = acc; acc += couts[q] * cinks[q];
    }
    wa.total = acc;
    wtrans_all_kernel<<<(acc + 255) / 256, 256>>>(wa, wt);
    enorm_kernel<<<KC/8, 256>>>(emb);

    // encoder
    conv1d_kernel<32, 64, 16, 2, 1, true ><<<dim3(NB,16), 64 >>>(x,  wt+WT0, eb0, h0, 512, 256, 512*32, 1,  32);
    conv1d_kernel<64, 128,16, 2, 1, true ><<<dim3(NB, 8), 128>>>(h0, wt+WT1, eb1, h1, 256, 128, 64*256, 256, 1);
    conv1d_kernel<128,256,16, 2, 1, true ><<<dim3(NB, 4), 256>>>(h1, wt+WT2, eb2, h2, 128, 64,  128*128,128, 1);
    proj_kernel<<<dim3(NB, 4), 256>>>(h2, wt+WTP, pb, ze);

    // vector quantizer
    vq_kernel<<<NB, 256, VQ_SMEM>>>(ze, emb, hn, ix);
    loss_gather_kernel<<<NB*TQ, 256>>>(ze, emb);

    // decoder
    deconv1d_kernel<256,256,16,1, true ><<<dim3(NB, 8), dim3(256,1)>>>(zq, wt+WTD0, db0, d0, 64,  256*128, 128, 1);
    deconv1d_kernel<256,128,16,1, true ><<<dim3(NB,16), dim3(128,1)>>>(d0, wt+WTD1, db1, d1, 128, 128*256, 256, 1);
    deconv1d_kernel<128,64, 16,2, true ><<<dim3(NB,16), dim3(64, 2)>>>(d1, wt+WTD2, db2, d2, 256, 64*512,  512, 1);
    deconv1d_kernel<64, 32, 16,4, false><<<dim3(NB,16), dim3(32, 4)>>>(d2, wt+WTD3, db3, out,512, 1024*32, 1,  32);

    // scalar outputs (indices + losses)
    idxout_kernel<<<64, 256>>>(out);
}

// round 4
// speedup vs baseline: 1.0039x; 1.0039x over previous
#include <cuda_runtime.h>

// ---------------- problem constants ----------------
#define NB   256      // batch
#define TQ   64       // quantized time
#define HD   256      // hidden dim
#define KC   8192     // n_embeddings

// output packing: (out, codebook_loss, commitment_loss, indices)
#define OUT_ELEMS   (256*1024*32)      // 8388608
#define LOSS_OFF    OUT_ELEMS
#define IDX_OFF     (OUT_ELEMS + 2)

// encoder/proj transposed-weight offsets (in g_wt)
#define WT0  0          // enc0 32*3*64   = 6144
#define WT1  6144       // enc1 64*3*128  = 24576
#define WT2  30720      // enc2 128*3*256 = 98304
#define WTP  129024     // proj 256*1*256 = 65536
#define WT_TOT 194560

// deconv duplicated-weight offsets (in g_wtd, u64 pairs stored as 2 floats)
#define WD0  0          // dec0 256*3*256*2 = 393216
#define WD1  393216     // dec1 256*3*128*2 = 196608
#define WD2  589824     // dec2 128*3*64*2  = 49152
#define WD3  638976     // dec3 64*3*32*2   = 12288
#define WD_TOT 651264

typedef unsigned long long u64;

// ---------------- f32x2 helpers (sm_103a packed fp32, bit-identical to 2x scalar) ----
__device__ __forceinline__ u64 ffma2(u64 a, u64 b, u64 c) {
    u64 d;
    asm("fma.rn.f32x2 %0, %1, %2, %3;" : "=l"(d) : "l"(a), "l"(b), "l"(c));
    return d;
}
__device__ __forceinline__ u64 pack2(float lo, float hi) {
    u64 d;
    asm("mov.b64 %0, {%1, %2};" : "=l"(d) : "f"(lo), "f"(hi));
    return d;
}
__device__ __forceinline__ float f2lo(u64 v) {
    float lo, hi;
    asm("mov.b64 {%0, %1}, %2;" : "=f"(lo), "=f"(hi) : "l"(v));
    return lo;
}
__device__ __forceinline__ float f2hi(u64 v) {
    float lo, hi;
    asm("mov.b64 {%0, %1}, %2;" : "=f"(lo), "=f"(hi) : "l"(v));
    return hi;
}
__device__ __forceinline__ void cp_async16(unsigned smem_addr, const void* gptr) {
    asm volatile("cp.async.cg.shared.global [%0], [%1], 16;" :: "r"(smem_addr), "l"(gptr));
}
__device__ __forceinline__ void cp_commit() {
    asm volatile("cp.async.commit_group;" ::: "memory");
}
__device__ __forceinline__ void cp_wait0() {
    asm volatile("cp.async.wait_group 0;" ::: "memory");
}

// ---------------- device scratch ----------------
__device__ float g_h0[256*64*256];
__device__ float g_h1[256*128*128];
__device__ float g_h2[256*256*64];
__device__ float g_ze[256*256*64];
__device__ float g_zq[256*256*64];
__device__ float g_d0[256*256*128];
__device__ float g_d1[256*128*256];
__device__ float g_d2[256*64*512];
__device__ float g_wt[WT_TOT];
__device__ float g_wtd[WD_TOT];
__device__ float g_embT[256*8192];     // transposed codebook [k][n]
__device__ float g_hn[KC];
__device__ int   g_idx[NB*TQ];
__device__ float g_loss[1];

// ---------------- combined weight transpose ----------------
// enc/proj (s<4):  wt[(ci*K+k)*Cout + co] = w[co][ci][k]
// deconv  (s>=4):  wtd[((ci*3+k)*Cout + co)*2 + {0,1}] = w  (duplicated pairs)
struct WtArgs {
    const float* src[8];
    int dst_off[8];
    int cout[8];
    int cink[8];
    int start[8];
    int total;
};
__global__ void wtrans_all_kernel(WtArgs a, float* __restrict__ wt, float* __restrict__ wtd) {
    int i = blockIdx.x * 256 + threadIdx.x;
    if (i >= a.total) return;
    int s = 0;
    #pragma unroll
    for (int q = 1; q < 8; q++) if (i >= a.start[q]) s = q;
    int e  = i - a.start[s];
    int co = e / a.cink[s];
    int r  = e - co * a.cink[s];
    float v = a.src[s][e];
    if (s < 4) {
        wt[a.dst_off[s] + r * a.cout[s] + co] = v;
    } else {
        int o = a.dst_off[s] + (r * a.cout[s] + co) * 2;
        wtd[o] = v; wtd[o + 1] = v;
    }
}

// ---------------- codebook transpose: emb[n][k] -> embT[k][n] ----------------
__global__ void etrans_kernel(const float* __restrict__ emb, float* __restrict__ embT) {
    __shared__ float t[32][33];
    int n0 = blockIdx.x * 32, k0 = blockIdx.y * 32;
    int tx = threadIdx.x, ty = threadIdx.y;   // 32 x 8
    #pragma unroll
    for (int i = 0; i < 4; i++)
        t[ty + 8 * i][tx] = emb[(long)(n0 + ty + 8 * i) * HD + k0 + tx];
    __syncthreads();
    #pragma unroll
    for (int i = 0; i < 4; i++)
        embT[(long)(k0 + ty + 8 * i) * KC + n0 + tx] = t[tx][ty + 8 * i];
}

// ---------------- 0.5*||e||^2 (+ zero loss accumulator) ----------------
__global__ void enorm_kernel(const float* __restrict__ emb) {
    if (blockIdx.x == 0 && threadIdx.x == 0) g_loss[0] = 0.f;
    int n = blockIdx.x * 8 + (threadIdx.x >> 5);
    int lane = threadIdx.x & 31;
    const float* e = emb + (long)n * HD;
    float s = 0.f;
    #pragma unroll
    for (int c = lane; c < HD; c += 32) { float v = e[c]; s += v * v; }
    #pragma unroll
    for (int o = 16; o; o >>= 1) s += __shfl_xor_sync(0xffffffffu, s, o);
    if (lane == 0) g_hn[n] = 0.5f * s;
}

// ---------------- generic direct conv1d (k=3, strided; encoder) ----------------
template<int CIN, int COUT, int TT, int STRIDE, int PAD, bool RELU>
__global__ void conv1d_kernel(const float* __restrict__ in, const float* __restrict__ wt,
                              const float* __restrict__ bias, float* __restrict__ out,
                              int Tin, int Tout, int inB, int inC, int inT) {
    const int SW = STRIDE * (TT - 1) + 3;
    __shared__ float s_in[CIN][SW];
    int b   = blockIdx.x;
    int to0 = blockIdx.y * TT;
    int ti0 = STRIDE * to0 - PAD;

    for (int idx = threadIdx.x; idx < CIN * SW; idx += blockDim.x) {
        int ci = idx / SW, j = idx - ci * SW;
        int tg = ti0 + j;
        s_in[ci][j] = (tg >= 0 && tg < Tin)
            ? in[(long)b * inB + (long)ci * inC + (long)tg * inT] : 0.f;
    }
    __syncthreads();

    int co = threadIdx.x;
    float acc[TT];
    float bv = bias[co];
    #pragma unroll
    for (int t = 0; t < TT; t++) acc[t] = bv;

    for (int ci = 0; ci < CIN; ci++) {
        const float* sr = s_in[ci];
        float w0 = wt[(ci * 3 + 0) * COUT + co];
        float w1 = wt[(ci * 3 + 1) * COUT + co];
        float w2 = wt[(ci * 3 + 2) * COUT + co];
        #pragma unroll
        for (int t = 0; t < TT; t++) {
            acc[t] = fmaf(w0, sr[STRIDE * t + 0], acc[t]);
            acc[t] = fmaf(w1, sr[STRIDE * t + 1], acc[t]);
            acc[t] = fmaf(w2, sr[STRIDE * t + 2], acc[t]);
        }
    }
    long ob = (long)b * COUT * Tout + (long)co * Tout + to0;
    #pragma unroll
    for (int t = 0; t < TT; t++) {
        float v = acc[t];
        if (RELU) v = fmaxf(v, 0.f);
        out[ob + t] = v;
    }
}

// ---------------- 1x1 projection conv, f32x2 ----------------
__global__ void proj_kernel(const float* __restrict__ in, const float* __restrict__ wt,
                            const float* __restrict__ bias, float* __restrict__ out) {
    __shared__ float s_in[256][16];
    int b   = blockIdx.x;
    int to0 = blockIdx.y * 16;
    for (int idx = threadIdx.x; idx < 256 * 16; idx += 256) {
        int ci = idx >> 4, j = idx & 15;
        s_in[ci][j] = in[(long)b * (256 * 64) + ci * 64 + to0 + j];
    }
    __syncthreads();

    int co = threadIdx.x;
    float bv = bias[co];
    u64 acc[8];
    #pragma unroll
    for (int p = 0; p < 8; p++) acc[p] = pack2(bv, bv);

    for (int ci = 0; ci < 256; ci++) {
        float w = wt[ci * 256 + co];
        u64 ws = pack2(w, w);
        const u64* xr = (const u64*)&s_in[ci][0];
        #pragma unroll
        for (int p = 0; p < 8; p++) acc[p] = ffma2(ws, xr[p], acc[p]);
    }
    long ob = (long)b * (256 * 64) + (long)co * 64 + to0;
    #pragma unroll
    for (int p = 0; p < 8; p++) {
        out[ob + 2 * p + 0] = f2lo(acc[p]);
        out[ob + 2 * p + 1] = f2hi(acc[p]);
    }
}

// ---------------- deconv (ConvTranspose1d k=3 s=2 p=1 op=1), f32x2, dup weights ----
// even to: w1*x[to/2]; odd to: w0*x[(to-1)/2] + w2*x[(to+1)/2]
// s_in[ci][j] = x[t0h+j]; s_sh[ci][j] = x[t0h+j+1] (shifted copy: aligned odd-tap LDS.64)
template<int CIN, int COUT, int TT, int G, bool RELU>
__global__ void deconv1d_kernel(const float* __restrict__ in, const float* __restrict__ wd_f,
                                const float* __restrict__ bias, float* __restrict__ out,
                                int Tin, long oB, long oCs, long oTs) {
    const int IW  = G * TT / 2 + 1;
    const int IWP = (IW | 1) + 1;       // even row stride (8B-aligned rows)
    const int IWL = IW + 1;
    __shared__ float s_in[CIN][IWP];
    __shared__ float s_sh[CIN][IWP];
    int b   = blockIdx.x;
    int to0 = blockIdx.y * (G * TT);
    int t0h = to0 >> 1;
    int nt  = blockDim.x * blockDim.y;
    int tid = threadIdx.y * blockDim.x + threadIdx.x;

    for (int idx = tid; idx < CIN * IWL; idx += nt) {
        int ci = idx / IWL, j = idx - ci * IWL;
        int tg = t0h + j;
        float v = (tg < Tin) ? in[(long)b * CIN * Tin + (long)ci * Tin + tg] : 0.f;
        if (j < IW) s_in[ci][j] = v;
        if (j > 0)  s_sh[ci][j - 1] = v;
    }
    __syncthreads();

    int co   = threadIdx.x;
    int base = threadIdx.y * TT;
    int H0   = base >> 1;                // even
    float bv = bias[co];
    u64 aE[TT / 4], aO[TT / 4];
    #pragma unroll
    for (int p = 0; p < TT / 4; p++) { aE[p] = pack2(bv, bv); aO[p] = pack2(bv, bv); }

    const u64* wd = (const u64*)wd_f;
    for (int ci = 0; ci < CIN; ci++) {
        u64 w0 = wd[(ci * 3 + 0) * COUT + co];
        u64 w1 = wd[(ci * 3 + 1) * COUT + co];
        u64 w2 = wd[(ci * 3 + 2) * COUT + co];
        #pragma unroll
        for (int p = 0; p < 4; p++) {
            u64 X = *(const u64*)&s_in[ci][H0 + 2 * p];
            u64 Z = *(const u64*)&s_sh[ci][H0 + 2 * p];
            aE[p] = ffma2(w1, X, aE[p]);
            aO[p] = ffma2(w0, X, aO[p]);
            aO[p] = ffma2(w2, Z, aO[p]);
        }
    }
    long ob = (long)b * oB + (long)co * oCs;
    #pragma unroll
    for (int p = 0; p < 4; p++) {
        float v0 = f2lo(aE[p]), v1 = f2lo(aO[p]), v2 = f2hi(aE[p]), v3 = f2hi(aO[p]);
        if (RELU) { v0 = fmaxf(v0, 0.f); v1 = fmaxf(v1, 0.f); v2 = fmaxf(v2, 0.f); v3 = fmaxf(v3, 0.f); }
        long t = to0 + base + 4 * p;
        out[ob + (t + 0) * oTs] = v0;
        out[ob + (t + 1) * oTs] = v1;
        out[ob + (t + 2) * oTs] = v2;
        out[ob + (t + 3) * oTs] = v3;
    }
}

// ---------------- VQ: fused GEMM (Z @ E^T) + argmax(score - 0.5||e||^2) --------------
// One CTA per batch (64 m rows). A duplicated in smem (zero-pack FFMA2 operand).
// B tiles (32 n wide, k-major) double-buffered via cp.async from pre-transposed embT:
// no register staging, no smem transpose. Per k per thread: 2 LDS.128 + 4 FFMA2.
#define BROW 36
#define VQ_SMEM (256*128*4 + 2*256*BROW*4)       // 131072 + 73728 = 204800
__global__ void vq_kernel(const float* __restrict__ ze, const float* __restrict__ embT,
                          const float* __restrict__ hn, int* __restrict__ out_idx) {
    extern __shared__ float sm[];
    float* Asd = sm;                       // [256][128]  Asd[k][2m]=Asd[k][2m+1]=z
    float* Bs0 = sm + 256 * 128;           // [256][BROW] k-major
    float* Bs1 = Bs0 + 256 * BROW;
    int b   = blockIdx.x;
    int tid = threadIdx.x;                 // 256
    int tx  = tid & 7;                     // n quad
    int ty  = tid >> 3;                    // m pair

    // ---- fill Asd (duplicated z tile), vectorized coalesced reads ----
    const float4* zb4 = (const float4*)(ze + (long)b * (HD * TQ));
    #pragma unroll
    for (int i = 0; i < 16; i++) {
        float4 v = zb4[i * 256 + tid];
        int el = 4 * (i * 256 + tid);      // el = k*64 + t, t multiple of 4
        int k = el >> 6, t = el & 63;
        u64* dst = (u64*)&Asd[k * 128 + 2 * t];
        dst[0] = pack2(v.x, v.x);
        dst[1] = pack2(v.y, v.y);
        dst[2] = pack2(v.z, v.z);
        dst[3] = pack2(v.w, v.w);
    }

    // ---- prefetch tile 0: thread tid owns k-row tid (128B contiguous) ----
    const float* myrow = embT + (long)tid * KC;
    {
        unsigned d = (unsigned)__cvta_generic_to_shared(Bs0 + tid * BROW);
        #pragma unroll
        for (int c = 0; c < 8; c++) cp_async16(d + 16u * c, myrow + 4 * c);
        cp_commit();
    }
    cp_wait0();
    __syncthreads();

    float bval0 = -3.4e38f, bval1 = -3.4e38f;
    int   bidx0 = 0,        bidx1 = 0;
    const float* ab = Asd + 4 * ty;

    for (int tile = 0; tile < KC / 32; tile++) {
        const float* cur = (tile & 1) ? Bs1 : Bs0;
        float*       nxt = (tile & 1) ? Bs0 : Bs1;

        if (tile + 1 < KC / 32) {          // async prefetch next tile
            const float* src = myrow + (tile + 1) * 32;
            unsigned d = (unsigned)__cvta_generic_to_shared(nxt + tid * BROW);
            #pragma unroll
            for (int c = 0; c < 8; c++) cp_async16(d + 16u * c, src + 4 * c);
            cp_commit();
        }

        u64 acc0 = 0ull, acc1 = 0ull, acc2 = 0ull, acc3 = 0ull;
        const float* bb = cur + 4 * tx;
        #pragma unroll 8
        for (int k = 0; k < HD; k++) {
            ulonglong2 av = *(const ulonglong2*)(ab + 128 * k);   // (a0,a0),(a1,a1)
            ulonglong2 bv = *(const ulonglong2*)(bb + BROW * k);  // (b0,b1),(b2,b3)
            acc0 = ffma2(av.x, bv.x, acc0);
            acc1 = ffma2(av.x, bv.y, acc1);
            acc2 = ffma2(av.y, bv.x, acc2);
            acc3 = ffma2(av.y, bv.y, acc3);
        }

        // scores & argmax (ascending n, strict >)
        int n0 = tile * 32 + 4 * tx;
        float4 h = *(const float4*)&hn[n0];
        {
            float s0 = f2lo(acc0) - h.x, s1 = f2hi(acc0) - h.y;
            float s2 = f2lo(acc1) - h.z, s3 = f2hi(acc1) - h.w;
            if (s0 > bval0) { bval0 = s0; bidx0 = n0 + 0; }
            if (s1 > bval0) { bval0 = s1; bidx0 = n0 + 1; }
            if (s2 > bval0) { bval0 = s2; bidx0 = n0 + 2; }
            if (s3 > bval0) { bval0 = s3; bidx0 = n0 + 3; }
        }
        {
            float s0 = f2lo(acc2) - h.x, s1 = f2hi(acc2) - h.y;
            float s2 = f2lo(acc3) - h.z, s3 = f2hi(acc3) - h.w;
            if (s0 > bval1) { bval1 = s0; bidx1 = n0 + 0; }
            if (s1 > bval1) { bval1 = s1; bidx1 = n0 + 1; }
            if (s2 > bval1) { bval1 = s2; bidx1 = n0 + 2; }
            if (s3 > bval1) { bval1 = s3; bidx1 = n0 + 3; }
        }

        cp_wait0();
        __syncthreads();
    }

    // ---- reduce over the 8 tx lanes sharing each m (tie-break: lower index) ----
    #pragma unroll
    for (int s = 1; s < 8; s <<= 1) {
        float ov0 = __shfl_xor_sync(0xffffffffu, bval0, s);
        int   oi0 = __shfl_xor_sync(0xffffffffu, bidx0, s);
        float ov1 = __shfl_xor_sync(0xffffffffu, bval1, s);
        int   oi1 = __shfl_xor_sync(0xffffffffu, bidx1, s);
        if (ov0 > bval0 || (ov0 == bval0 && oi0 < bidx0)) { bval0 = ov0; bidx0 = oi0; }
        if (ov1 > bval1 || (ov1 == bval1 && oi1 < bidx1)) { bval1 = ov1; bidx1 = oi1; }
    }
    if (tx == 0) {
        out_idx[b * 64 + 2 * ty]     = bidx0;
        out_idx[b * 64 + 2 * ty + 1] = bidx1;
    }
}

// ---------------- gather z_q + loss sum ----------------
__global__ void loss_gather_kernel(const float* __restrict__ ze, const float* __restrict__ emb) {
    int m = blockIdx.x;
    int b = m >> 6, t = m & 63;
    int c = threadIdx.x;                      // 256
    int e = g_idx[m];
    float q = emb[(long)e * HD + c];
    long zoff = (long)b * (HD * TQ) + (long)c * TQ + t;
    float z = ze[zoff];
    g_zq[zoff] = q;
    float d = z - q;
    float s = d * d;
    #pragma unroll
    for (int o = 16; o; o >>= 1) s += __shfl_down_sync(0xffffffffu, s, o);
    __shared__ float ws[8];
    if ((c & 31) == 0) ws[c >> 5] = s;
    __syncthreads();
    if (c == 0) {
        float tot = 0.f;
        #pragma unroll
        for (int i = 0; i < 8; i++) tot += ws[i];
        atomicAdd(g_loss, tot);
    }
}

// ---------------- indices + losses to output ----------------
__global__ void idxout_kernel(float* out) {
    int m = blockIdx.x * 256 + threadIdx.x;
    out[IDX_OFF + m] = (float)g_idx[m];
    if (m == 0) {
        float l = g_loss[0] * (1.f / 4194304.f);   // mean over B*H*TQ
        out[LOSS_OFF + 0] = l;
        out[LOSS_OFF + 1] = l;
    }
}

// ---------------- launch ----------------
extern "C" void kernel_launch(void* const* d_in, const int* in_sizes, int n_in,
                              void* d_out, int out_size) {
    const float* x   = (const float*)d_in[0];
    const float* ew0 = (const float*)d_in[1];  const float* eb0 = (const float*)d_in[2];
    const float* ew1 = (const float*)d_in[3];  const float* eb1 = (const float*)d_in[4];
    const float* ew2 = (const float*)d_in[5];  const float* eb2 = (const float*)d_in[6];
    const float* pw  = (const float*)d_in[7];  const float* pb  = (const float*)d_in[8];
    const float* emb = (const float*)d_in[9];
    const float* dw0 = (const float*)d_in[10]; const float* db0 = (const float*)d_in[11];
    const float* dw1 = (const float*)d_in[12]; const float* db1 = (const float*)d_in[13];
    const float* dw2 = (const float*)d_in[14]; const float* db2 = (const float*)d_in[15];
    const float* dw3 = (const float*)d_in[16]; const float* db3 = (const float*)d_in[17];
    float* out = (float*)d_out;

    void* p;
    cudaGetSymbolAddress(&p, g_wt);   float* wt  = (float*)p;
    cudaGetSymbolAddress(&p, g_wtd);  float* wtd = (float*)p;
    cudaGetSymbolAddress(&p, g_embT); float* embT= (float*)p;
    cudaGetSymbolAddress(&p, g_h0);   float* h0  = (float*)p;
    cudaGetSymbolAddress(&p, g_h1);   float* h1  = (float*)p;
    cudaGetSymbolAddress(&p, g_h2);   float* h2  = (float*)p;
    cudaGetSymbolAddress(&p, g_ze);   float* ze  = (float*)p;
    cudaGetSymbolAddress(&p, g_zq);   float* zq  = (float*)p;
    cudaGetSymbolAddress(&p, g_d0);   float* d0  = (float*)p;
    cudaGetSymbolAddress(&p, g_d1);   float* d1  = (float*)p;
    cudaGetSymbolAddress(&p, g_d2);   float* d2  = (float*)p;
    cudaGetSymbolAddress(&p, g_hn);   float* hn  = (float*)p;
    cudaGetSymbolAddress(&p, g_idx);  int*   ix  = (int*)p;

    cudaFuncSetAttribute(vq_kernel, cudaFuncAttributeMaxDynamicSharedMemorySize, VQ_SMEM);

    // prep: weight transposes (enc plain, dec duplicated), codebook transpose, norms
    WtArgs wa;
    const float* srcs[8] = {ew0, ew1, ew2, pw, dw0, dw1, dw2, dw3};
    int offs[8]  = {WT0, WT1, WT2, WTP, WD0, WD1, WD2, WD3};
    int couts[8] = {64, 128, 256, 256, 256, 128, 64, 32};
    int cinks[8] = {32*3, 64*3, 128*3, 256, 256*3, 256*3, 128*3, 64*3};
    int acc = 0;
    for (int q = 0; q < 8; q++) {
        wa.src[q] = srcs[q]; wa.dst_off[q] = offs[q];
        wa.cout[q] = couts[q]; wa.cink[q] = cinks[q];
        wa.start[q] = acc; acc += couts[q] * cinks[q];
    }
    wa.total = acc;
    wtrans_all_kernel<<<(acc + 255) / 256, 256>>>(wa, wt, wtd);
    etrans_kernel<<<dim3(KC/32, HD/32), dim3(32, 8)>>>(emb, embT);
    enorm_kernel<<<KC/8, 256>>>(emb);

    // encoder
    conv1d_kernel<32, 64, 16, 2, 1, true ><<<dim3(NB,16), 64 >>>(x,  wt+WT0, eb0, h0, 512, 256, 512*32, 1,  32);
    conv1d_kernel<64, 128,16, 2, 1, true ><<<dim3(NB, 8), 128>>>(h0, wt+WT1, eb1, h1, 256, 128, 64*256, 256, 1);
    conv1d_kernel<128,256,16, 2, 1, true ><<<dim3(NB, 4), 256>>>(h1, wt+WT2, eb2, h2, 128, 64,  128*128,128, 1);
    proj_kernel<<<dim3(NB, 4), 256>>>(h2, wt+WTP, pb, ze);

    // vector quantizer
    vq_kernel<<<NB, 256, VQ_SMEM>>>(ze, embT, hn, ix);
    loss_gather_kernel<<<NB*TQ, 256>>>(ze, emb);

    // decoder
    deconv1d_kernel<256,256,16,1, true ><<<dim3(NB, 8), dim3(256,1)>>>(zq, wtd+WD0, db0, d0, 64,  256*128, 128, 1);
    deconv1d_kernel<256,128,16,1, true ><<<dim3(NB,16), dim3(128,1)>>>(d0, wtd+WD1, db1, d1, 128, 128*256, 256, 1);
    deconv1d_kernel<128,64, 16,2, true ><<<dim3(NB,16), dim3(64, 2)>>>(d1, wtd+WD2, db2, d2, 256, 64*512,  512, 1);
    deconv1d_kernel<64, 32, 16,4, false><<<dim3(NB,16), dim3(32, 4)>>>(d2, wtd+WD3, db3, out,512, 1024*32, 1,  32);

    // scalar outputs (indices + losses)
    idxout_kernel<<<64, 256>>>(out);
}

// round 7
// speedup vs baseline: 1.0060x; 1.0021x over previous
#include <cuda_runtime.h>

// ---------------- problem constants ----------------
#define NB   256      // batch
#define TQ   64       // quantized time
#define HD   256      // hidden dim
#define KC   8192     // n_embeddings

// output packing: (out, codebook_loss, commitment_loss, indices)
#define OUT_ELEMS   (256*1024*32)      // 8388608
#define LOSS_OFF    OUT_ELEMS
#define IDX_OFF     (OUT_ELEMS + 2)

// encoder/proj transposed-weight offsets (in g_wt)
#define WT0  0          // enc0 32*3*64   = 6144
#define WT1  6144       // enc1 64*3*128  = 24576
#define WT2  30720      // enc2 128*3*256 = 98304
#define WTP  129024     // proj 256*1*256 = 65536
#define WT_TOT 194560

// deconv duplicated-weight offsets (in g_wtd, u64 pairs stored as 2 floats)
#define WD0  0          // dec0 256*3*256*2 = 393216
#define WD1  393216     // dec1 256*3*128*2 = 196608
#define WD2  589824     // dec2 128*3*64*2  = 49152
#define WD3  638976     // dec3 64*3*32*2   = 12288
#define WD_TOT 651264

typedef unsigned long long u64;

// ---------------- f32x2 helpers (sm_103a packed fp32, bit-identical to 2x scalar) ----
__device__ __forceinline__ u64 ffma2(u64 a, u64 b, u64 c) {
    u64 d;
    asm("fma.rn.f32x2 %0, %1, %2, %3;" : "=l"(d) : "l"(a), "l"(b), "l"(c));
    return d;
}
__device__ __forceinline__ u64 pack2(float lo, float hi) {
    u64 d;
    asm("mov.b64 %0, {%1, %2};" : "=l"(d) : "f"(lo), "f"(hi));
    return d;
}
__device__ __forceinline__ float f2lo(u64 v) {
    float lo, hi;
    asm("mov.b64 {%0, %1}, %2;" : "=f"(lo), "=f"(hi) : "l"(v));
    return lo;
}
__device__ __forceinline__ float f2hi(u64 v) {
    float lo, hi;
    asm("mov.b64 {%0, %1}, %2;" : "=f"(lo), "=f"(hi) : "l"(v));
    return hi;
}
__device__ __forceinline__ void cp_async16(unsigned smem_addr, const void* gptr) {
    asm volatile("cp.async.cg.shared.global [%0], [%1], 16;" :: "r"(smem_addr), "l"(gptr));
}
__device__ __forceinline__ void cp_commit() {
    asm volatile("cp.async.commit_group;" ::: "memory");
}
__device__ __forceinline__ void cp_wait0() {
    asm volatile("cp.async.wait_group 0;" ::: "memory");
}

// ---------------- device scratch ----------------
__device__ float g_h0[256*64*256];
__device__ float g_h1[256*128*128];
__device__ float g_h2[256*256*64];
__device__ float g_ze[256*256*64];
__device__ float g_zq[256*256*64];
__device__ float g_d0[256*256*128];
__device__ float g_d1[256*128*256];
__device__ float g_d2[256*64*512];
__device__ float g_wt[WT_TOT];
__device__ float g_wtd[WD_TOT];
__device__ float g_embT[256*8192];     // transposed codebook [k][n]
__device__ float g_hn[KC];
__device__ int   g_idx[NB*TQ];
__device__ float g_loss[1];

// ---------------- combined weight transpose ----------------
// enc/proj (s<4):  wt[(ci*K+k)*Cout + co] = w[co][ci][k]
// deconv  (s>=4):  wtd[((ci*3+k)*Cout + co)*2 + {0,1}] = w  (duplicated pairs)
struct WtArgs {
    const float* src[8];
    int dst_off[8];
    int cout[8];
    int cink[8];
    int start[8];
    int total;
};
__global__ void wtrans_all_kernel(WtArgs a, float* __restrict__ wt, float* __restrict__ wtd) {
    int i = blockIdx.x * 256 + threadIdx.x;
    if (i >= a.total) return;
    int s = 0;
    #pragma unroll
    for (int q = 1; q < 8; q++) if (i >= a.start[q]) s = q;
    int e  = i - a.start[s];
    int co = e / a.cink[s];
    int r  = e - co * a.cink[s];
    float v = a.src[s][e];
    if (s < 4) {
        wt[a.dst_off[s] + r * a.cout[s] + co] = v;
    } else {
        int o = a.dst_off[s] + (r * a.cout[s] + co) * 2;
        wtd[o] = v; wtd[o + 1] = v;
    }
}

// ---------------- codebook transpose: emb[n][k] -> embT[k][n] ----------------
__global__ void etrans_kernel(const float* __restrict__ emb, float* __restrict__ embT) {
    __shared__ float t[32][33];
    int n0 = blockIdx.x * 32, k0 = blockIdx.y * 32;
    int tx = threadIdx.x, ty = threadIdx.y;   // 32 x 8
    #pragma unroll
    for (int i = 0; i < 4; i++)
        t[ty + 8 * i][tx] = emb[(long)(n0 + ty + 8 * i) * HD + k0 + tx];
    __syncthreads();
    #pragma unroll
    for (int i = 0; i < 4; i++)
        embT[(long)(k0 + ty + 8 * i) * KC + n0 + tx] = t[tx][ty + 8 * i];
}

// ---------------- 0.5*||e||^2 (+ zero loss accumulator) ----------------
__global__ void enorm_kernel(const float* __restrict__ emb) {
    if (blockIdx.x == 0 && threadIdx.x == 0) g_loss[0] = 0.f;
    int n = blockIdx.x * 8 + (threadIdx.x >> 5);
    int lane = threadIdx.x & 31;
    const float* e = emb + (long)n * HD;
    float s = 0.f;
    #pragma unroll
    for (int c = lane; c < HD; c += 32) { float v = e[c]; s += v * v; }
    #pragma unroll
    for (int o = 16; o; o >>= 1) s += __shfl_xor_sync(0xffffffffu, s, o);
    if (lane == 0) g_hn[n] = 0.5f * s;
}

// ---------------- generic direct conv1d (k=3, strided; encoder) ----------------
template<int CIN, int COUT, int TT, int STRIDE, int PAD, bool RELU>
__global__ void conv1d_kernel(const float* __restrict__ in, const float* __restrict__ wt,
                              const float* __restrict__ bias, float* __restrict__ out,
                              int Tin, int Tout, int inB, int inC, int inT) {
    const int SW = STRIDE * (TT - 1) + 3;
    __shared__ float s_in[CIN][SW];
    int b   = blockIdx.x;
    int to0 = blockIdx.y * TT;
    int ti0 = STRIDE * to0 - PAD;

    for (int idx = threadIdx.x; idx < CIN * SW; idx += blockDim.x) {
        int ci = idx / SW, j = idx - ci * SW;
        int tg = ti0 + j;
        s_in[ci][j] = (tg >= 0 && tg < Tin)
            ? in[(long)b * inB + (long)ci * inC + (long)tg * inT] : 0.f;
    }
    __syncthreads();

    int co = threadIdx.x;
    float acc[TT];
    float bv = bias[co];
    #pragma unroll
    for (int t = 0; t < TT; t++) acc[t] = bv;

    for (int ci = 0; ci < CIN; ci++) {
        const float* sr = s_in[ci];
        float w0 = wt[(ci * 3 + 0) * COUT + co];
        float w1 = wt[(ci * 3 + 1) * COUT + co];
        float w2 = wt[(ci * 3 + 2) * COUT + co];
        #pragma unroll
        for (int t = 0; t < TT; t++) {
            acc[t] = fmaf(w0, sr[STRIDE * t + 0], acc[t]);
            acc[t] = fmaf(w1, sr[STRIDE * t + 1], acc[t]);
            acc[t] = fmaf(w2, sr[STRIDE * t + 2], acc[t]);
        }
    }
    long ob = (long)b * COUT * Tout + (long)co * Tout + to0;
    #pragma unroll
    for (int t = 0; t < TT; t++) {
        float v = acc[t];
        if (RELU) v = fmaxf(v, 0.f);
        out[ob + t] = v;
    }
}

// ---------------- 1x1 projection conv, f32x2 ----------------
__global__ void proj_kernel(const float* __restrict__ in, const float* __restrict__ wt,
                            const float* __restrict__ bias, float* __restrict__ out) {
    __shared__ float s_in[256][16];
    int b   = blockIdx.x;
    int to0 = blockIdx.y * 16;
    for (int idx = threadIdx.x; idx < 256 * 16; idx += 256) {
        int ci = idx >> 4, j = idx & 15;
        s_in[ci][j] = in[(long)b * (256 * 64) + ci * 64 + to0 + j];
    }
    __syncthreads();

    int co = threadIdx.x;
    float bv = bias[co];
    u64 acc[8];
    #pragma unroll
    for (int p = 0; p < 8; p++) acc[p] = pack2(bv, bv);

    for (int ci = 0; ci < 256; ci++) {
        float w = wt[ci * 256 + co];
        u64 ws = pack2(w, w);
        const u64* xr = (const u64*)&s_in[ci][0];
        #pragma unroll
        for (int p = 0; p < 8; p++) acc[p] = ffma2(ws, xr[p], acc[p]);
    }
    long ob = (long)b * (256 * 64) + (long)co * 64 + to0;
    #pragma unroll
    for (int p = 0; p < 8; p++) {
        out[ob + 2 * p + 0] = f2lo(acc[p]);
        out[ob + 2 * p + 1] = f2hi(acc[p]);
    }
}

// ---------------- deconv (ConvTranspose1d k=3 s=2 p=1 op=1), f32x2, dup weights ----
// even to: w1*x[to/2]; odd to: w0*x[(to-1)/2] + w2*x[(to+1)/2]
// s_in[ci][j] = x[t0h+j]; s_sh[ci][j] = x[t0h+j+1] (shifted copy: aligned odd-tap LDS.64)
template<int CIN, int COUT, int TT, int G, bool RELU>
__global__ void deconv1d_kernel(const float* __restrict__ in, const float* __restrict__ wd_f,
                                const float* __restrict__ bias, float* __restrict__ out,
                                int Tin, long oB, long oCs, long oTs) {
    const int IW  = G * TT / 2 + 1;
    const int IWP = (IW | 1) + 1;       // even row stride (8B-aligned rows)
    const int IWL = IW + 1;
    __shared__ float s_in[CIN][IWP];
    __shared__ float s_sh[CIN][IWP];
    int b   = blockIdx.x;
    int to0 = blockIdx.y * (G * TT);
    int t0h = to0 >> 1;
    int nt  = blockDim.x * blockDim.y;
    int tid = threadIdx.y * blockDim.x + threadIdx.x;

    for (int idx = tid; idx < CIN * IWL; idx += nt) {
        int ci = idx / IWL, j = idx - ci * IWL;
        int tg = t0h + j;
        float v = (tg < Tin) ? in[(long)b * CIN * Tin + (long)ci * Tin + tg] : 0.f;
        if (j < IW) s_in[ci][j] = v;
        if (j > 0)  s_sh[ci][j - 1] = v;
    }
    __syncthreads();

    int co   = threadIdx.x;
    int base = threadIdx.y * TT;
    int H0   = base >> 1;                // even
    float bv = bias[co];
    u64 aE[TT / 4], aO[TT / 4];
    #pragma unroll
    for (int p = 0; p < TT / 4; p++) { aE[p] = pack2(bv, bv); aO[p] = pack2(bv, bv); }

    const u64* wd = (const u64*)wd_f;
    for (int ci = 0; ci < CIN; ci++) {
        u64 w0 = wd[(ci * 3 + 0) * COUT + co];
        u64 w1 = wd[(ci * 3 + 1) * COUT + co];
        u64 w2 = wd[(ci * 3 + 2) * COUT + co];
        #pragma unroll
        for (int p = 0; p < 4; p++) {
            u64 X = *(const u64*)&s_in[ci][H0 + 2 * p];
            u64 Z = *(const u64*)&s_sh[ci][H0 + 2 * p];
            aE[p] = ffma2(w1, X, aE[p]);
            aO[p] = ffma2(w0, X, aO[p]);
            aO[p] = ffma2(w2, Z, aO[p]);
        }
    }
    long ob = (long)b * oB + (long)co * oCs;
    #pragma unroll
    for (int p = 0; p < 4; p++) {
        float v0 = f2lo(aE[p]), v1 = f2lo(aO[p]), v2 = f2hi(aE[p]), v3 = f2hi(aO[p]);
        if (RELU) { v0 = fmaxf(v0, 0.f); v1 = fmaxf(v1, 0.f); v2 = fmaxf(v2, 0.f); v3 = fmaxf(v3, 0.f); }
        long t = to0 + base + 4 * p;
        out[ob + (t + 0) * oTs] = v0;
        out[ob + (t + 1) * oTs] = v1;
        out[ob + (t + 2) * oTs] = v2;
        out[ob + (t + 3) * oTs] = v3;
    }
}

// ---------------- VQ: fused GEMM (Z @ E^T) + argmax(score - 0.5||e||^2) --------------
// One CTA per batch (64 m rows). A duplicated in smem (zero-pack FFMA2 operand).
// B tiles (32 n wide, k-major) double-buffered via cp.async from pre-transposed embT:
// no register staging, no smem transpose. Per k per thread: 2 LDS.128 + 4 FFMA2.
#define BROW 36
#define VQ_SMEM (256*128*4 + 2*256*BROW*4)       // 131072 + 73728 = 204800
__global__ void vq_kernel(const float* __restrict__ ze, const float* __restrict__ embT,
                          const float* __restrict__ hn, int* __restrict__ out_idx) {
    extern __shared__ float sm[];
    float* Asd = sm;                       // [256][128]  Asd[k][2m]=Asd[k][2m+1]=z
    float* Bs0 = sm + 256 * 128;           // [256][BROW] k-major
    float* Bs1 = Bs0 + 256 * BROW;
    int b   = blockIdx.x;
    int tid = threadIdx.x;                 // 256
    int tx  = tid & 7;                     // n quad
    int ty  = tid >> 3;                    // m pair

    // ---- fill Asd (duplicated z tile), vectorized coalesced reads ----
    const float4* zb4 = (const float4*)(ze + (long)b * (HD * TQ));
    #pragma unroll
    for (int i = 0; i < 16; i++) {
        float4 v = zb4[i * 256 + tid];
        int el = 4 * (i * 256 + tid);      // el = k*64 + t, t multiple of 4
        int k = el >> 6, t = el & 63;
        u64* dst = (u64*)&Asd[k * 128 + 2 * t];
        dst[0] = pack2(v.x, v.x);
        dst[1] = pack2(v.y, v.y);
        dst[2] = pack2(v.z, v.z);
        dst[3] = pack2(v.w, v.w);
    }

    // ---- prefetch tile 0: thread tid owns k-row tid (128B contiguous) ----
    const float* myrow = embT + (long)tid * KC;
    {
        unsigned d = (unsigned)__cvta_generic_to_shared(Bs0 + tid * BROW);
        #pragma unroll
        for (int c = 0; c < 8; c++) cp_async16(d + 16u * c, myrow + 4 * c);
        cp_commit();
    }
    cp_wait0();
    __syncthreads();

    float bval0 = -3.4e38f, bval1 = -3.4e38f;
    int   bidx0 = 0,        bidx1 = 0;
    const float* ab = Asd + 4 * ty;

    for (int tile = 0; tile < KC / 32; tile++) {
        const float* cur = (tile & 1) ? Bs1 : Bs0;
        float*       nxt = (tile & 1) ? Bs0 : Bs1;

        if (tile + 1 < KC / 32) {          // async prefetch next tile
            const float* src = myrow + (tile + 1) * 32;
            unsigned d = (unsigned)__cvta_generic_to_shared(nxt + tid * BROW);
            #pragma unroll
            for (int c = 0; c < 8; c++) cp_async16(d + 16u * c, src + 4 * c);
            cp_commit();
        }

        u64 acc0 = 0ull, acc1 = 0ull, acc2 = 0ull, acc3 = 0ull;
        const float* bb = cur + 4 * tx;
        #pragma unroll 8
        for (int k = 0; k < HD; k++) {
            ulonglong2 av = *(const ulonglong2*)(ab + 128 * k);   // (a0,a0),(a1,a1)
            ulonglong2 bv = *(const ulonglong2*)(bb + BROW * k);  // (b0,b1),(b2,b3)
            acc0 = ffma2(av.x, bv.x, acc0);
            acc1 = ffma2(av.x, bv.y, acc1);
            acc2 = ffma2(av.y, bv.x, acc2);
            acc3 = ffma2(av.y, bv.y, acc3);
        }

        // scores & argmax (ascending n, strict >)
        int n0 = tile * 32 + 4 * tx;
        float4 h = *(const float4*)&hn[n0];
        {
            float s0 = f2lo(acc0) - h.x, s1 = f2hi(acc0) - h.y;
            float s2 = f2lo(acc1) - h.z, s3 = f2hi(acc1) - h.w;
            if (s0 > bval0) { bval0 = s0; bidx0 = n0 + 0; }
            if (s1 > bval0) { bval0 = s1; bidx0 = n0 + 1; }
            if (s2 > bval0) { bval0 = s2; bidx0 = n0 + 2; }
            if (s3 > bval0) { bval0 = s3; bidx0 = n0 + 3; }
        }
        {
            float s0 = f2lo(acc2) - h.x, s1 = f2hi(acc2) - h.y;
            float s2 = f2lo(acc3) - h.z, s3 = f2hi(acc3) - h.w;
            if (s0 > bval1) { bval1 = s0; bidx1 = n0 + 0; }
            if (s1 > bval1) { bval1 = s1; bidx1 = n0 + 1; }
            if (s2 > bval1) { bval1 = s2; bidx1 = n0 + 2; }
            if (s3 > bval1) { bval1 = s3; bidx1 = n0 + 3; }
        }

        cp_wait0();
        __syncthreads();
    }

    // ---- reduce over the 8 tx lanes sharing each m (tie-break: lower index) ----
    #pragma unroll
    for (int s = 1; s < 8; s <<= 1) {
        float ov0 = __shfl_xor_sync(0xffffffffu, bval0, s);
        int   oi0 = __shfl_xor_sync(0xffffffffu, bidx0, s);
        float ov1 = __shfl_xor_sync(0xffffffffu, bval1, s);
        int   oi1 = __shfl_xor_sync(0xffffffffu, bidx1, s);
        if (ov0 > bval0 || (ov0 == bval0 && oi0 < bidx0)) { bval0 = ov0; bidx0 = oi0; }
        if (ov1 > bval1 || (ov1 == bval1 && oi1 < bidx1)) { bval1 = ov1; bidx1 = oi1; }
    }
    if (tx == 0) {
        out_idx[b * 64 + 2 * ty]     = bidx0;
        out_idx[b * 64 + 2 * ty + 1] = bidx1;
    }
}

// ---------------- gather z_q + loss sum ----------------
__global__ void loss_gather_kernel(const float* __restrict__ ze, const float* __restrict__ emb) {
    int m = blockIdx.x;
    int b = m >> 6, t = m & 63;
    int c = threadIdx.x;                      // 256
    int e = g_idx[m];
    float q = emb[(long)e * HD + c];
    long zoff = (long)b * (HD * TQ) + (long)c * TQ + t;
    float z = ze[zoff];
    g_zq[zoff] = q;
    float d = z - q;
    float s = d * d;
    #pragma unroll
    for (int o = 16; o; o >>= 1) s += __shfl_down_sync(0xffffffffu, s, o);
    __shared__ float ws[8];
    if ((c & 31) == 0) ws[c >> 5] = s;
    __syncthreads();
    if (c == 0) {
        float tot = 0.f;
        #pragma unroll
        for (int i = 0; i < 8; i++) tot += ws[i];
        atomicAdd(g_loss, tot);
    }
}

// ---------------- indices + losses to output ----------------
__global__ void idxout_kernel(float* out) {
    int m = blockIdx.x * 256 + threadIdx.x;
    out[IDX_OFF + m] = (float)g_idx[m];
    if (m == 0) {
        float l = g_loss[0] * (1.f / 4194304.f);   // mean over B*H*TQ
        out[LOSS_OFF + 0] = l;
        out[LOSS_OFF + 1] = l;
    }
}

// ---------------- launch ----------------
extern "C" void kernel_launch(void* const* d_in, const int* in_sizes, int n_in,
                              void* d_out, int out_size) {
    const float* x   = (const float*)d_in[0];
    const float* ew0 = (const float*)d_in[1];  const float* eb0 = (const float*)d_in[2];
    const float* ew1 = (const float*)d_in[3];  const float* eb1 = (const float*)d_in[4];
    const float* ew2 = (const float*)d_in[5];  const float* eb2 = (const float*)d_in[6];
    const float* pw  = (const float*)d_in[7];  const float* pb  = (const float*)d_in[8];
    const float* emb = (const float*)d_in[9];
    const float* dw0 = (const float*)d_in[10]; const float* db0 = (const float*)d_in[11];
    const float* dw1 = (const float*)d_in[12]; const float* db1 = (const float*)d_in[13];
    const float* dw2 = (const float*)d_in[14]; const float* db2 = (const float*)d_in[15];
    const float* dw3 = (const float*)d_in[16]; const float* db3 = (const float*)d_in[17];
    float* out = (float*)d_out;

    void* p;
    cudaGetSymbolAddress(&p, g_wt);   float* wt  = (float*)p;
    cudaGetSymbolAddress(&p, g_wtd);  float* wtd = (float*)p;
    cudaGetSymbolAddress(&p, g_embT); float* embT= (float*)p;
    cudaGetSymbolAddress(&p, g_h0);   float* h0  = (float*)p;
    cudaGetSymbolAddress(&p, g_h1);   float* h1  = (float*)p;
    cudaGetSymbolAddress(&p, g_h2);   float* h2  = (float*)p;
    cudaGetSymbolAddress(&p, g_ze);   float* ze  = (float*)p;
    cudaGetSymbolAddress(&p, g_zq);   float* zq  = (float*)p;
    cudaGetSymbolAddress(&p, g_d0);   float* d0  = (float*)p;
    cudaGetSymbolAddress(&p, g_d1);   float* d1  = (float*)p;
    cudaGetSymbolAddress(&p, g_d2);   float* d2  = (float*)p;
    cudaGetSymbolAddress(&p, g_hn);   float* hn  = (float*)p;
    cudaGetSymbolAddress(&p, g_idx);  int*   ix  = (int*)p;

    cudaFuncSetAttribute(vq_kernel, cudaFuncAttributeMaxDynamicSharedMemorySize, VQ_SMEM);

    // prep: weight transposes (enc plain, dec duplicated), codebook transpose, norms
    WtArgs wa;
    const float* srcs[8] = {ew0, ew1, ew2, pw, dw0, dw1, dw2, dw3};
    int offs[8]  = {WT0, WT1, WT2, WTP, WD0, WD1, WD2, WD3};
    int couts[8] = {64, 128, 256, 256, 256, 128, 64, 32};
    int cinks[8] = {32*3, 64*3, 128*3, 256, 256*3, 256*3, 128*3, 64*3};
    int acc = 0;
    for (int q = 0; q < 8; q++) {
        wa.src[q] = srcs[q]; wa.dst_off[q] = offs[q];
        wa.cout[q] = couts[q]; wa.cink[q] = cinks[q];
        wa.start[q] = acc; acc += couts[q] * cinks[q];
    }
    wa.total = acc;
    wtrans_all_kernel<<<(acc + 255) / 256, 256>>>(wa, wt, wtd);
    etrans_kernel<<<dim3(KC/32, HD/32), dim3(32, 8)>>>(emb, embT);
    enorm_kernel<<<KC/8, 256>>>(emb);

    // encoder
    conv1d_kernel<32, 64, 16, 2, 1, true ><<<dim3(NB,16), 64 >>>(x,  wt+WT0, eb0, h0, 512, 256, 512*32, 1,  32);
    conv1d_kernel<64, 128,16, 2, 1, true ><<<dim3(NB, 8), 128>>>(h0, wt+WT1, eb1, h1, 256, 128, 64*256, 256, 1);
    conv1d_kernel<128,256,16, 2, 1, true ><<<dim3(NB, 4), 256>>>(h1, wt+WT2, eb2, h2, 128, 64,  128*128,128, 1);
    proj_kernel<<<dim3(NB, 4), 256>>>(h2, wt+WTP, pb, ze);

    // vector quantizer
    vq_kernel<<<NB, 256, VQ_SMEM>>>(ze, embT, hn, ix);
    loss_gather_kernel<<<NB*TQ, 256>>>(ze, emb);

    // decoder
    deconv1d_kernel<256,256,16,1, true ><<<dim3(NB, 8), dim3(256,1)>>>(zq, wtd+WD0, db0, d0, 64,  256*128, 128, 1);
    deconv1d_kernel<256,128,16,1, true ><<<dim3(NB,16), dim3(128,1)>>>(d0, wtd+WD1, db1, d1, 128, 128*256, 256, 1);
    deconv1d_kernel<128,64, 16,2, true ><<<dim3(NB,16), dim3(64, 2)>>>(d1, wtd+WD2, db2, d2, 256, 64*512,  512, 1);
    deconv1d_kernel<64, 32, 16,4, false><<<dim3(NB,16), dim3(32, 4)>>>(d2, wtd+WD3, db3, out,512, 1024*32, 1,  32);

    // scalar outputs (indices + losses)
    idxout_kernel<<<64, 256>>>(out);
}

// round 11
// speedup vs baseline: 1.2160x; 1.2087x over previous
#include <cuda_runtime.h>
#include <cuda_bf16.h>
#include <cstdint>

// ---------------- problem constants ----------------
#define NB   256      // batch
#define TQ   64       // quantized time
#define HD   256      // hidden dim
#define KC   8192     // n_embeddings

// output packing: (out, codebook_loss, commitment_loss, indices)
#define OUT_ELEMS   (256*1024*32)      // 8388608
#define LOSS_OFF    OUT_ELEMS
#define IDX_OFF     (OUT_ELEMS + 2)

// encoder/proj transposed-weight offsets (in g_wt)
#define WT0  0
#define WT1  6144
#define WT2  30720
#define WTP  129024
#define WT_TOT 194560

// deconv duplicated-weight offsets (in g_wtd)
#define WD0  0
#define WD1  393216
#define WD2  589824
#define WD3  638976
#define WD_TOT 651264

typedef unsigned long long u64;

// ---------------- f32x2 helpers ----------------
__device__ __forceinline__ u64 ffma2(u64 a, u64 b, u64 c) {
    u64 d;
    asm("fma.rn.f32x2 %0, %1, %2, %3;" : "=l"(d) : "l"(a), "l"(b), "l"(c));
    return d;
}
__device__ __forceinline__ u64 pack2(float lo, float hi) {
    u64 d;
    asm("mov.b64 %0, {%1, %2};" : "=l"(d) : "f"(lo), "f"(hi));
    return d;
}
__device__ __forceinline__ float f2lo(u64 v) {
    float lo, hi; asm("mov.b64 {%0, %1}, %2;" : "=f"(lo), "=f"(hi) : "l"(v)); return lo;
}
__device__ __forceinline__ float f2hi(u64 v) {
    float lo, hi; asm("mov.b64 {%0, %1}, %2;" : "=f"(lo), "=f"(hi) : "l"(v)); return hi;
}
__device__ __forceinline__ void cp_async16(unsigned smem_addr, const void* gptr) {
    asm volatile("cp.async.cg.shared.global [%0], [%1], 16;" :: "r"(smem_addr), "l"(gptr));
}
__device__ __forceinline__ void cp_commit() { asm volatile("cp.async.commit_group;" ::: "memory"); }

// ---------------- mma.sync helpers (sm_80-era, valid on baseline sm_103) ----------
__device__ __forceinline__ uint32_t smem_to_u32(const void* smem_ptr) {
    uint32_t addr;
    asm("{ .reg .u64 tmp; cvta.to.shared.u64 tmp, %1; cvt.u32.u64 %0, tmp; }"
        : "=r"(addr) : "l"(smem_ptr));
    return addr;
}
__device__ __forceinline__ void ldsm4(uint32_t* r, uint32_t addr) {
    asm volatile("ldmatrix.sync.aligned.m8n8.x4.shared.b16 {%0,%1,%2,%3}, [%4];"
        : "=r"(r[0]), "=r"(r[1]), "=r"(r[2]), "=r"(r[3]) : "r"(addr));
}
__device__ __forceinline__ void mma_bf16(float* c, const uint32_t* a, const uint32_t* b) {
    asm volatile(
        "mma.sync.aligned.m16n8k16.row.col.f32.bf16.bf16.f32 "
        "{%0,%1,%2,%3}, {%4,%5,%6,%7}, {%8,%9}, {%0,%1,%2,%3};"
        : "+f"(c[0]), "+f"(c[1]), "+f"(c[2]), "+f"(c[3])
        : "r"(a[0]), "r"(a[1]), "r"(a[2]), "r"(a[3]), "r"(b[0]), "r"(b[1]));
}

// ---------------- device scratch ----------------
__device__ float g_h0[256*64*256];
__device__ float g_h1[256*128*128];
__device__ float g_h2[256*256*64];
__device__ float g_ze[256*256*64];
__device__ float g_zq[256*256*64];
__device__ float g_d0[256*256*128];
__device__ float g_d1[256*128*256];
__device__ float g_d2[256*64*512];
__device__ float g_wt[WT_TOT];
__device__ float g_wtd[WD_TOT];
__device__ __nv_bfloat16 g_eb0[8192*256];   // codebook hi split  [n][k]
__device__ __nv_bfloat16 g_eb1[8192*256];   // codebook residual  [n][k]
__device__ float g_hn[KC];
__device__ int   g_idx[NB*TQ];
__device__ float g_loss[1];
__device__ int   g_flagcnt[1];
__device__ int   g_flagrows[16384];

// ---------------- combined weight transpose ----------------
struct WtArgs {
    const float* src[8];
    int dst_off[8];
    int cout[8];
    int cink[8];
    int start[8];
    int total;
};
__global__ void wtrans_all_kernel(WtArgs a, float* __restrict__ wt, float* __restrict__ wtd) {
    int i = blockIdx.x * 256 + threadIdx.x;
    if (i >= a.total) return;
    int s = 0;
    #pragma unroll
    for (int q = 1; q < 8; q++) if (i >= a.start[q]) s = q;
    int e  = i - a.start[s];
    int co = e / a.cink[s];
    int r  = e - co * a.cink[s];
    float v = a.src[s][e];
    if (s < 4) {
        wt[a.dst_off[s] + r * a.cout[s] + co] = v;
    } else {
        int o = a.dst_off[s] + (r * a.cout[s] + co) * 2;
        wtd[o] = v; wtd[o + 1] = v;
    }
}

// ---------------- codebook bf16 split (plain [n][k] layout) ----------------
__global__ void ebsplit_kernel(const float* __restrict__ emb,
                               __nv_bfloat16* __restrict__ e0, __nv_bfloat16* __restrict__ e1) {
    int i = blockIdx.x * 256 + threadIdx.x;
    float v = emb[i];
    __nv_bfloat16 h0 = __float2bfloat16(v);
    __nv_bfloat16 h1 = __float2bfloat16(v - __bfloat162float(h0));
    e0[i] = h0;
    e1[i] = h1;
}

// ---------------- 0.5*||e||^2 (+ zero accumulators) ----------------
__global__ void enorm_kernel(const float* __restrict__ emb) {
    if (blockIdx.x == 0 && threadIdx.x == 0) { g_loss[0] = 0.f; g_flagcnt[0] = 0; }
    int n = blockIdx.x * 8 + (threadIdx.x >> 5);
    int lane = threadIdx.x & 31;
    const float* e = emb + (long)n * HD;
    float s = 0.f;
    #pragma unroll
    for (int c = lane; c < HD; c += 32) { float v = e[c]; s += v * v; }
    #pragma unroll
    for (int o = 16; o; o >>= 1) s += __shfl_xor_sync(0xffffffffu, s, o);
    if (lane == 0) g_hn[n] = 0.5f * s;
}

// ---------------- generic direct conv1d (k=3, strided; encoder) ----------------
template<int CIN, int COUT, int TT, int STRIDE, int PAD, bool RELU>
__global__ void conv1d_kernel(const float* __restrict__ in, const float* __restrict__ wt,
                              const float* __restrict__ bias, float* __restrict__ out,
                              int Tin, int Tout, int inB, int inC, int inT) {
    const int SW = STRIDE * (TT - 1) + 3;
    __shared__ float s_in[CIN][SW];
    int b   = blockIdx.x;
    int to0 = blockIdx.y * TT;
    int ti0 = STRIDE * to0 - PAD;

    for (int idx = threadIdx.x; idx < CIN * SW; idx += blockDim.x) {
        int ci = idx / SW, j = idx - ci * SW;
        int tg = ti0 + j;
        s_in[ci][j] = (tg >= 0 && tg < Tin)
            ? in[(long)b * inB + (long)ci * inC + (long)tg * inT] : 0.f;
    }
    __syncthreads();

    int co = threadIdx.x;
    float acc[TT];
    float bv = bias[co];
    #pragma unroll
    for (int t = 0; t < TT; t++) acc[t] = bv;

    for (int ci = 0; ci < CIN; ci++) {
        const float* sr = s_in[ci];
        float w0 = wt[(ci * 3 + 0) * COUT + co];
        float w1 = wt[(ci * 3 + 1) * COUT + co];
        float w2 = wt[(ci * 3 + 2) * COUT + co];
        #pragma unroll
        for (int t = 0; t < TT; t++) {
            acc[t] = fmaf(w0, sr[STRIDE * t + 0], acc[t]);
            acc[t] = fmaf(w1, sr[STRIDE * t + 1], acc[t]);
            acc[t] = fmaf(w2, sr[STRIDE * t + 2], acc[t]);
        }
    }
    long ob = (long)b * COUT * Tout + (long)co * Tout + to0;
    #pragma unroll
    for (int t = 0; t < TT; t++) {
        float v = acc[t];
        if (RELU) v = fmaxf(v, 0.f);
        out[ob + t] = v;
    }
}

// ---------------- 1x1 projection conv, f32x2 ----------------
__global__ void proj_kernel(const float* __restrict__ in, const float* __restrict__ wt,
                            const float* __restrict__ bias, float* __restrict__ out) {
    __shared__ float s_in[256][16];
    int b   = blockIdx.x;
    int to0 = blockIdx.y * 16;
    for (int idx = threadIdx.x; idx < 256 * 16; idx += 256) {
        int ci = idx >> 4, j = idx & 15;
        s_in[ci][j] = in[(long)b * (256 * 64) + ci * 64 + to0 + j];
    }
    __syncthreads();

    int co = threadIdx.x;
    float bv = bias[co];
    u64 acc[8];
    #pragma unroll
    for (int p = 0; p < 8; p++) acc[p] = pack2(bv, bv);

    for (int ci = 0; ci < 256; ci++) {
        float w = wt[ci * 256 + co];
        u64 ws = pack2(w, w);
        const u64* xr = (const u64*)&s_in[ci][0];
        #pragma unroll
        for (int p = 0; p < 8; p++) acc[p] = ffma2(ws, xr[p], acc[p]);
    }
    long ob = (long)b * (256 * 64) + (long)co * 64 + to0;
    #pragma unroll
    for (int p = 0; p < 8; p++) {
        out[ob + 2 * p + 0] = f2lo(acc[p]);
        out[ob + 2 * p + 1] = f2hi(acc[p]);
    }
}

// ---------------- deconv (ConvTranspose1d k=3 s=2 p=1 op=1), f32x2, dup weights ----
template<int CIN, int COUT, int TT, int G, bool RELU>
__global__ void deconv1d_kernel(const float* __restrict__ in, const float* __restrict__ wd_f,
                                const float* __restrict__ bias, float* __restrict__ out,
                                int Tin, long oB, long oCs, long oTs) {
    const int IW  = G * TT / 2 + 1;
    const int IWP = (IW | 1) + 1;
    const int IWL = IW + 1;
    __shared__ float s_in[CIN][IWP];
    __shared__ float s_sh[CIN][IWP];
    int b   = blockIdx.x;
    int to0 = blockIdx.y * (G * TT);
    int t0h = to0 >> 1;
    int nt  = blockDim.x * blockDim.y;
    int tid = threadIdx.y * blockDim.x + threadIdx.x;

    for (int idx = tid; idx < CIN * IWL; idx += nt) {
        int ci = idx / IWL, j = idx - ci * IWL;
        int tg = t0h + j;
        float v = (tg < Tin) ? in[(long)b * CIN * Tin + (long)ci * Tin + tg] : 0.f;
        if (j < IW) s_in[ci][j] = v;
        if (j > 0)  s_sh[ci][j - 1] = v;
    }
    __syncthreads();

    int co   = threadIdx.x;
    int base = threadIdx.y * TT;
    int H0   = base >> 1;
    float bv = bias[co];
    u64 aE[TT / 4], aO[TT / 4];
    #pragma unroll
    for (int p = 0; p < TT / 4; p++) { aE[p] = pack2(bv, bv); aO[p] = pack2(bv, bv); }

    const u64* wd = (const u64*)wd_f;
    for (int ci = 0; ci < CIN; ci++) {
        u64 w0 = wd[(ci * 3 + 0) * COUT + co];
        u64 w1 = wd[(ci * 3 + 1) * COUT + co];
        u64 w2 = wd[(ci * 3 + 2) * COUT + co];
        #pragma unroll
        for (int p = 0; p < 4; p++) {
            u64 X = *(const u64*)&s_in[ci][H0 + 2 * p];
            u64 Z = *(const u64*)&s_sh[ci][H0 + 2 * p];
            aE[p] = ffma2(w1, X, aE[p]);
            aO[p] = ffma2(w0, X, aO[p]);
            aO[p] = ffma2(w2, Z, aO[p]);
        }
    }
    long ob = (long)b * oB + (long)co * oCs;
    #pragma unroll
    for (int p = 0; p < 4; p++) {
        float v0 = f2lo(aE[p]), v1 = f2lo(aO[p]), v2 = f2hi(aE[p]), v3 = f2hi(aO[p]);
        if (RELU) { v0 = fmaxf(v0, 0.f); v1 = fmaxf(v1, 0.f); v2 = fmaxf(v2, 0.f); v3 = fmaxf(v3, 0.f); }
        long t = to0 + base + 4 * p;
        out[ob + (t + 0) * oTs] = v0;
        out[ob + (t + 1) * oTs] = v1;
        out[ob + (t + 2) * oTs] = v2;
        out[ob + (t + 3) * oTs] = v3;
    }
}

// ---------------- VQ: mma.sync bf16 3-pass split GEMM + argmax + top-2 margin ------
// CTA = 256 thr (8 warps: 4 x m16, 2 x n32), one batch (64 rows). Grid = 256.
// Smem: A splits (XOR-swizzled, 64x256 bf16 x2) + B double-buffered (64x256 x2 splits)
// + hn fp32. Swizzle: 16B-chunk c at row r -> c ^ (r&7).
#define VQ_A0   0
#define VQ_A1   32768
#define VQ_BOFF 65536
#define VQ_HN   196608
#define VQT_SMEM 229376
#define VQ_BST(stage, split) (VQ_BOFF + ((stage) * 2 + (split)) * 32768)

__device__ __forceinline__ void vq_fill_stage(uint32_t smem_base, int stage, int tile,
                                              const __nv_bfloat16* e0, const __nv_bfloat16* e1,
                                              int tid) {
    uint32_t b0 = smem_base + VQ_BST(stage, 0);
    uint32_t b1 = smem_base + VQ_BST(stage, 1);
    #pragma unroll
    for (int i = 0; i < 8; i++) {
        int c = tid + i * 256;             // 2048 chunks of 16B per split
        int row = c >> 5, cc = c & 31;
        uint32_t dst = (uint32_t)(row * 512) + (uint32_t)((cc ^ (row & 7)) << 4);
        long srcoff = ((long)tile * 64 + row) * 256 + cc * 8;
        cp_async16(b0 + dst, e0 + srcoff);
        cp_async16(b1 + dst, e1 + srcoff);
    }
}

__global__ __launch_bounds__(256, 1)
void vq_mma_kernel(const float* __restrict__ ze,
                   const __nv_bfloat16* __restrict__ e0, const __nv_bfloat16* __restrict__ e1,
                   const float* __restrict__ hn, int* __restrict__ out_idx,
                   int* __restrict__ flag_cnt, int* __restrict__ flag_rows) {
    extern __shared__ char smem[];
    uint32_t smem_base = smem_to_u32(smem);
    int tid = threadIdx.x;
    int cta = blockIdx.x;                   // batch index

    // prefetch B tile 0 first (overlaps A conversion)
    vq_fill_stage(smem_base, 0, 0, e0, e1, tid);
    cp_commit();

    // ---- A fill: z -> bf16 splits, swizzled smem ----
    {
        int m = tid & 63, kseg = tid >> 6;  // 4 threads per row, 64 k each
        const float* zb = ze + (long)cta * (HD * TQ);
        for (int kk = 0; kk < 64; kk++) {
            int k = kseg * 64 + kk;
            float v = zb[k * 64 + m];       // coalesced across m
            __nv_bfloat16 h0 = __float2bfloat16(v);
            __nv_bfloat16 h1 = __float2bfloat16(v - __bfloat162float(h0));
            uint32_t off = (uint32_t)(m * 512) + (uint32_t)((((k >> 3) ^ (m & 7)) << 4) + (k & 7) * 2);
            *(__nv_bfloat16*)(smem + VQ_A0 + off) = h0;
            *(__nv_bfloat16*)(smem + VQ_A1 + off) = h1;
        }
    }
    // ---- hn -> smem ----
    {
        float4* hs = (float4*)(smem + VQ_HN);
        const float4* hg = (const float4*)hn;
        #pragma unroll
        for (int i = 0; i < 8; i++) hs[tid + i * 256] = hg[tid + i * 256];
    }
    asm volatile("cp.async.wait_group 0;" ::: "memory");
    __syncthreads();

    // ---- per-thread fragment address precompute ----
    int lane = tid & 31, wid = tid >> 5;
    int wm = wid & 3, wn = wid >> 2;
    // A ldmatrix: lanes 0-7: m0-7@klo; 8-15: m8-15@klo; 16-23: m0-7@khi; 24-31: m8-15@khi
    int mrow = wm * 16 + (lane & 15);
    int khiA = lane >> 4;
    uint32_t aRow = (uint32_t)(mrow * 512);
    int r7A = mrow & 7;
    // B ldmatrix: g0: n0-7@klo; g1: n0-7@khi; g2: n8-15@klo; g3: n8-15@khi
    int nl   = (lane & 7) | ((lane >> 1) & 8);
    int khiB = (lane >> 3) & 1;
    int nrow0 = wn * 32 + nl;
    int nrow1 = nrow0 + 16;
    uint32_t bRow0 = (uint32_t)(nrow0 * 512);
    uint32_t bRow1 = (uint32_t)(nrow1 * 512);
    int r7B0 = nrow0 & 7, r7B1 = nrow1 & 7;

    float best0 = -3.4e38f, sec0 = -3.4e38f, best1 = -3.4e38f, sec1 = -3.4e38f;
    int   idx0 = 0, idx1 = 0;
    const float* hns = (const float*)(smem + VQ_HN);

    for (int tile = 0; tile < 128; tile++) {
        int stage = tile & 1;
        if (tile + 1 < 128) {
            vq_fill_stage(smem_base, stage ^ 1, tile + 1, e0, e1, tid);
            cp_commit();
            asm volatile("cp.async.wait_group 1;" ::: "memory");
        } else {
            asm volatile("cp.async.wait_group 0;" ::: "memory");
        }
        __syncthreads();

        uint32_t sb0 = smem_base + VQ_BST(stage, 0);
        uint32_t sb1 = smem_base + VQ_BST(stage, 1);

        float acc[4][4];
        #pragma unroll
        for (int j = 0; j < 4; j++)
            #pragma unroll
            for (int q = 0; q < 4; q++) acc[j][q] = 0.f;

        #pragma unroll
        for (int ks = 0; ks < 16; ks++) {
            uint32_t a0[4], a1[4], b0[8], b1l[4];
            uint32_t offA = (uint32_t)(((2 * ks + khiA) ^ r7A) << 4);
            ldsm4(a0, smem_base + VQ_A0 + aRow + offA);
            ldsm4(a1, smem_base + VQ_A1 + aRow + offA);
            uint32_t cB = (uint32_t)(2 * ks + khiB);
            uint32_t offB0 = ((cB ^ (uint32_t)r7B0) << 4) + bRow0;
            uint32_t offB1 = ((cB ^ (uint32_t)r7B1) << 4) + bRow1;
            ldsm4(b0 + 0, sb0 + offB0);     // split0: n 0-15 of warp's 32
            ldsm4(b0 + 4, sb0 + offB1);     // split0: n 16-31
            ldsm4(b1l + 0, sb1 + offB0);    // split1: n 0-15
            // pass z0*e0 + z1*e0
            #pragma unroll
            for (int j = 0; j < 4; j++) {
                mma_bf16(acc[j], a0, b0 + (j >> 1) * 4 + (j & 1) * 2);
                mma_bf16(acc[j], a1, b0 + (j >> 1) * 4 + (j & 1) * 2);
            }
            // pass z0*e1 (n 0-15 with b1l, n 16-31 loaded next)
            mma_bf16(acc[0], a0, b1l + 0);
            mma_bf16(acc[1], a0, b1l + 2);
            ldsm4(b1l, sb1 + offB1);        // split1: n 16-31 (reuse regs)
            mma_bf16(acc[2], a0, b1l + 0);
            mma_bf16(acc[3], a0, b1l + 2);
        }

        // epilogue: scores & top-2 update (ascending n within thread)
        int nb = tile * 64 + wn * 32 + (lane & 3) * 2;
        #pragma unroll
        for (int j = 0; j < 4; j++) {
            int n = nb + j * 8;
            float h0v = hns[n], h1v = hns[n + 1];
            float s0 = acc[j][0] - h0v, s1 = acc[j][1] - h1v;
            float s2 = acc[j][2] - h0v, s3 = acc[j][3] - h1v;
            if (s0 > best0) { sec0 = best0; best0 = s0; idx0 = n; }     else if (s0 > sec0) sec0 = s0;
            if (s1 > best0) { sec0 = best0; best0 = s1; idx0 = n + 1; } else if (s1 > sec0) sec0 = s1;
            if (s2 > best1) { sec1 = best1; best1 = s2; idx1 = n; }     else if (s2 > sec1) sec1 = s2;
            if (s3 > best1) { sec1 = best1; best1 = s3; idx1 = n + 1; } else if (s3 > sec1) sec1 = s3;
        }
        __syncthreads();
    }

    // ---- cross-lane merge within 4-lane row groups ----
    #pragma unroll
    for (int o = 1; o < 4; o <<= 1) {
        float ob = __shfl_xor_sync(0xffffffffu, best0, o);
        float os = __shfl_xor_sync(0xffffffffu, sec0, o);
        int   oi = __shfl_xor_sync(0xffffffffu, idx0, o);
        if (ob > best0)       { sec0 = fmaxf(best0, os); best0 = ob; idx0 = oi; }
        else if (ob == best0) { sec0 = best0; idx0 = min(idx0, oi); }
        else                  { sec0 = fmaxf(sec0, ob); }
        ob = __shfl_xor_sync(0xffffffffu, best1, o);
        os = __shfl_xor_sync(0xffffffffu, sec1, o);
        oi = __shfl_xor_sync(0xffffffffu, idx1, o);
        if (ob > best1)       { sec1 = fmaxf(best1, os); best1 = ob; idx1 = oi; }
        else if (ob == best1) { sec1 = best1; idx1 = min(idx1, oi); }
        else                  { sec1 = fmaxf(sec1, ob); }
    }

    // ---- cross-warp (wn) reduce via smem (A region is free now) ----
    float* rb = (float*)smem;            // [64][2]
    float* rs = rb + 128;                // [64][2]
    int*   ri = (int*)(rb + 256);        // [64][2]
    if ((lane & 3) == 0) {
        int r0 = wm * 16 + (lane >> 2);
        rb[r0 * 2 + wn] = best0; rs[r0 * 2 + wn] = sec0; ri[r0 * 2 + wn] = idx0;
        int r1 = r0 + 8;
        rb[r1 * 2 + wn] = best1; rs[r1 * 2 + wn] = sec1; ri[r1 * 2 + wn] = idx1;
    }
    __syncthreads();
    if (tid < 64) {
        float b = rb[tid * 2], s = rs[tid * 2];
        int   i = ri[tid * 2];
        float ob = rb[tid * 2 + 1], os = rs[tid * 2 + 1];
        int   oi = ri[tid * 2 + 1];
        if (ob > b)       { s = fmaxf(b, os); b = ob; i = oi; }
        else if (ob == b) { s = b; i = min(i, oi); }
        else              { s = fmaxf(s, ob); }
        int gr = cta * 64 + tid;
        out_idx[gr] = i;
        if (b - s < 0.02f) {
            int sl = atomicAdd(flag_cnt, 1);
            flag_rows[sl] = gr;
        }
    }
}

// ---------------- exact fp32 rescore of margin-flagged rows ----------------
__global__ void vq_fallback_kernel(const float* __restrict__ ze, const float* __restrict__ emb,
                                   const float* __restrict__ hn) {
    if ((int)blockIdx.x >= g_flagcnt[0]) return;
    __shared__ float zrow[256];
    __shared__ float rv[256];
    __shared__ int   ri[256];
    int r = g_flagrows[blockIdx.x];
    int b = r >> 6, t = r & 63;
    int k = threadIdx.x;
    zrow[k] = ze[(long)b * (HD * TQ) + k * TQ + t];
    __syncthreads();
    float best = -3.4e38f; int bidx = 0;
    for (int n = k; n < KC; n += 256) {
        const float* e = emb + (long)n * HD;
        float s = -hn[n];
        #pragma unroll 8
        for (int kk = 0; kk < HD; kk++) s = fmaf(zrow[kk], e[kk], s);
        if (s > best) { best = s; bidx = n; }
    }
    rv[k] = best; ri[k] = bidx;
    __syncthreads();
    if (k == 0) {
        float bv = rv[0]; int bi = ri[0];
        for (int j = 1; j < 256; j++)
            if (rv[j] > bv || (rv[j] == bv && ri[j] < bi)) { bv = rv[j]; bi = ri[j]; }
        g_idx[r] = bi;
    }
}

// ---------------- gather z_q + loss sum ----------------
__global__ void loss_gather_kernel(const float* __restrict__ ze, const float* __restrict__ emb) {
    int m = blockIdx.x;
    int b = m >> 6, t = m & 63;
    int c = threadIdx.x;
    int e = g_idx[m];
    float q = emb[(long)e * HD + c];
    long zoff = (long)b * (HD * TQ) + (long)c * TQ + t;
    float z = ze[zoff];
    g_zq[zoff] = q;
    float d = z - q;
    float s = d * d;
    #pragma unroll
    for (int o = 16; o; o >>= 1) s += __shfl_down_sync(0xffffffffu, s, o);
    __shared__ float ws[8];
    if ((c & 31) == 0) ws[c >> 5] = s;
    __syncthreads();
    if (c == 0) {
        float tot = 0.f;
        #pragma unroll
        for (int i = 0; i < 8; i++) tot += ws[i];
        atomicAdd(g_loss, tot);
    }
}

// ---------------- indices + losses to output ----------------
__global__ void idxout_kernel(float* out) {
    int m = blockIdx.x * 256 + threadIdx.x;
    out[IDX_OFF + m] = (float)g_idx[m];
    if (m == 0) {
        float l = g_loss[0] * (1.f / 4194304.f);
        out[LOSS_OFF + 0] = l;
        out[LOSS_OFF + 1] = l;
    }
}

// ---------------- launch ----------------
extern "C" void kernel_launch(void* const* d_in, const int* in_sizes, int n_in,
                              void* d_out, int out_size) {
    const float* x   = (const float*)d_in[0];
    const float* ew0 = (const float*)d_in[1];  const float* eb0b = (const float*)d_in[2];
    const float* ew1 = (const float*)d_in[3];  const float* eb1b = (const float*)d_in[4];
    const float* ew2 = (const float*)d_in[5];  const float* eb2b = (const float*)d_in[6];
    const float* pw  = (const float*)d_in[7];  const float* pb   = (const float*)d_in[8];
    const float* emb = (const float*)d_in[9];
    const float* dw0 = (const float*)d_in[10]; const float* db0 = (const float*)d_in[11];
    const float* dw1 = (const float*)d_in[12]; const float* db1 = (const float*)d_in[13];
    const float* dw2 = (const float*)d_in[14]; const float* db2 = (const float*)d_in[15];
    const float* dw3 = (const float*)d_in[16]; const float* db3 = (const float*)d_in[17];
    float* out = (float*)d_out;

    void* p;
    cudaGetSymbolAddress(&p, g_wt);   float* wt  = (float*)p;
    cudaGetSymbolAddress(&p, g_wtd);  float* wtd = (float*)p;
    cudaGetSymbolAddress(&p, g_eb0);  __nv_bfloat16* e0 = (__nv_bfloat16*)p;
    cudaGetSymbolAddress(&p, g_eb1);  __nv_bfloat16* e1 = (__nv_bfloat16*)p;
    cudaGetSymbolAddress(&p, g_h0);   float* h0  = (float*)p;
    cudaGetSymbolAddress(&p, g_h1);   float* h1  = (float*)p;
    cudaGetSymbolAddress(&p, g_h2);   float* h2  = (float*)p;
    cudaGetSymbolAddress(&p, g_ze);   float* ze  = (float*)p;
    cudaGetSymbolAddress(&p, g_zq);   float* zq  = (float*)p;
    cudaGetSymbolAddress(&p, g_d0);   float* d0  = (float*)p;
    cudaGetSymbolAddress(&p, g_d1);   float* d1  = (float*)p;
    cudaGetSymbolAddress(&p, g_d2);   float* d2  = (float*)p;
    cudaGetSymbolAddress(&p, g_hn);   float* hn  = (float*)p;
    cudaGetSymbolAddress(&p, g_idx);  int*   ix  = (int*)p;
    cudaGetSymbolAddress(&p, g_flagcnt);  int* fcnt = (int*)p;
    cudaGetSymbolAddress(&p, g_flagrows); int* frow = (int*)p;

    cudaFuncSetAttribute(vq_mma_kernel, cudaFuncAttributeMaxDynamicSharedMemorySize, VQT_SMEM);

    // prep
    WtArgs wa;
    const float* srcs[8] = {ew0, ew1, ew2, pw, dw0, dw1, dw2, dw3};
    int offs[8]  = {WT0, WT1, WT2, WTP, WD0, WD1, WD2, WD3};
    int couts[8] = {64, 128, 256, 256, 256, 128, 64, 32};
    int cinks[8] = {32*3, 64*3, 128*3, 256, 256*3, 256*3, 128*3, 64*3};
    int acc = 0;
    for (int q = 0; q < 8; q++) {
        wa.src[q] = srcs[q]; wa.dst_off[q] = offs[q];
        wa.cout[q] = couts[q]; wa.cink[q] = cinks[q];
        wa.start[q] = acc; acc += couts[q] * cinks[q];
    }
    wa.total = acc;
    wtrans_all_kernel<<<(acc + 255) / 256, 256>>>(wa, wt, wtd);
    ebsplit_kernel<<<(KC * HD) / 256, 256>>>(emb, e0, e1);
    enorm_kernel<<<KC/8, 256>>>(emb);

    // encoder
    conv1d_kernel<32, 64, 16, 2, 1, true ><<<dim3(NB,16), 64 >>>(x,  wt+WT0, eb0b, h0, 512, 256, 512*32, 1,  32);
    conv1d_kernel<64, 128,16, 2, 1, true ><<<dim3(NB, 8), 128>>>(h0, wt+WT1, eb1b, h1, 256, 128, 64*256, 256, 1);
    conv1d_kernel<128,256,16, 2, 1, true ><<<dim3(NB, 4), 256>>>(h1, wt+WT2, eb2b, h2, 128, 64,  128*128,128, 1);
    proj_kernel<<<dim3(NB, 4), 256>>>(h2, wt+WTP, pb, ze);

    // vector quantizer (tensor core + exact fallback)
    vq_mma_kernel<<<NB, 256, VQT_SMEM>>>(ze, e0, e1, hn, ix, fcnt, frow);
    vq_fallback_kernel<<<16384, 256>>>(ze, emb, hn);
    loss_gather_kernel<<<NB*TQ, 256>>>(ze, emb);

    // decoder
    deconv1d_kernel<256,256,16,1, true ><<<dim3(NB, 8), dim3(256,1)>>>(zq, wtd+WD0, db0, d0, 64,  256*128, 128, 1);
    deconv1d_kernel<256,128,16,1, true ><<<dim3(NB,16), dim3(128,1)>>>(d0, wtd+WD1, db1, d1, 128, 128*256, 256, 1);
    deconv1d_kernel<128,64, 16,2, true ><<<dim3(NB,16), dim3(64, 2)>>>(d1, wtd+WD2, db2, d2, 256, 64*512,  512, 1);
    deconv1d_kernel<64, 32, 16,4, false><<<dim3(NB,16), dim3(32, 4)>>>(d2, wtd+WD3, db3, out,512, 1024*32, 1,  32);

    // scalar outputs
    idxout_kernel<<<64, 256>>>(out);
}